// round 2
// baseline (speedup 1.0000x reference)
#include <cuda_runtime.h>
#include <math.h>

#define BQ   2
#define SQ   2048
#define DIM  1024
#define HQ   16
#define DH   64
#define GQ   16
#define IQ   256
#define MROW (BQ*SQ)   /* 4096 */

// ---------------- device scratch (no allocations allowed) ----------------
__device__ float g_WT[4][DIM*DIM];     // W_eff^T per projection, [k][n] layout
__device__ float g_q[MROW*DIM];
__device__ float g_k[MROW*DIM];
__device__ float g_v[MROW*DIM];
__device__ float g_attn[MROW*DIM];

// ---------------- build effective quaternion weight (transposed) ----------
// out[r, n] = sum_k x[r,k] * W[n,k];  WT[k*DIM + n] = W[n,k]
// n = 4m+c (output), k = 4p+d (input). Hamilton table:
//  c=0: [ wr, -wi, -wj, -wk]
//  c=1: [ wi,  wr, -wj,  wk]
//  c=2: [ wj,  wi,  wr, -wk]
//  c=3: [ wk, -wi,  wj,  wr]
__global__ void build_wt_kernel(const float* __restrict__ wr,
                                const float* __restrict__ wi,
                                const float* __restrict__ wj,
                                const float* __restrict__ wk,
                                float* __restrict__ WT) {
    int idx = blockIdx.x * blockDim.x + threadIdx.x;   // 0 .. DIM*DIM-1
    int k = idx >> 10;
    int n = idx & 1023;
    int m = n >> 2, c = n & 3;
    int p = k >> 2, d = k & 3;

    const int   comp[4][4] = {{0,1,2,3},{1,0,2,3},{2,1,0,3},{3,1,2,0}};
    const float sgn [4][4] = {{ 1.f,-1.f,-1.f,-1.f},
                              { 1.f, 1.f,-1.f, 1.f},
                              { 1.f, 1.f, 1.f,-1.f},
                              { 1.f,-1.f, 1.f, 1.f}};
    const float* ws[4] = {wr, wi, wj, wk};
    WT[idx] = sgn[c][d] * ws[comp[c][d]][m * IQ + p];
}

// ---------------- SGEMM: C[M,N] = A[M,K] @ WT (K-major) + bias ------------
// BM=128, BN=128, BK=8, 256 threads, 8x8 per thread.
#define BM 128
#define BN 128
#define BK 8
__global__ __launch_bounds__(256) void sgemm_kernel(
    const float* __restrict__ A, const float* __restrict__ Bt,
    const float* __restrict__ bias, float* __restrict__ C) {
    const int K = DIM, N = DIM;
    __shared__ float As[BK][BM];
    __shared__ float Bs[BK][BN];

    int tid = threadIdx.x;
    int bm = blockIdx.y * BM;
    int bn = blockIdx.x * BN;
    int tx = tid & 15;        // 0..15
    int ty = tid >> 4;        // 0..15

    int a_m = tid >> 1;             // 0..127
    int a_k = (tid & 1) * 4;        // 0 or 4
    int b_k = tid >> 5;             // 0..7
    int b_n = (tid & 31) * 4;       // 0..124

    float acc[8][8];
    #pragma unroll
    for (int i = 0; i < 8; i++)
        #pragma unroll
        for (int j = 0; j < 8; j++) acc[i][j] = 0.f;

    for (int k0 = 0; k0 < K; k0 += BK) {
        float4 av = *(const float4*)&A[(size_t)(bm + a_m) * K + k0 + a_k];
        As[a_k + 0][a_m] = av.x;
        As[a_k + 1][a_m] = av.y;
        As[a_k + 2][a_m] = av.z;
        As[a_k + 3][a_m] = av.w;
        *(float4*)&Bs[b_k][b_n] = *(const float4*)&Bt[(size_t)(k0 + b_k) * N + bn + b_n];
        __syncthreads();

        #pragma unroll
        for (int kk = 0; kk < BK; kk++) {
            float ar[8], br[8];
            *(float4*)&ar[0] = *(const float4*)&As[kk][ty * 8 + 0];
            *(float4*)&ar[4] = *(const float4*)&As[kk][ty * 8 + 4];
            *(float4*)&br[0] = *(const float4*)&Bs[kk][tx * 8 + 0];
            *(float4*)&br[4] = *(const float4*)&Bs[kk][tx * 8 + 4];
            #pragma unroll
            for (int i = 0; i < 8; i++)
                #pragma unroll
                for (int j = 0; j < 8; j++)
                    acc[i][j] += ar[i] * br[j];
        }
        __syncthreads();
    }

    #pragma unroll
    for (int i = 0; i < 8; i++) {
        int row = bm + ty * 8 + i;
        #pragma unroll
        for (int j = 0; j < 8; j += 4) {
            int col = bn + tx * 8 + j;
            float4 o;
            o.x = acc[i][j + 0] + bias[col + 0];
            o.y = acc[i][j + 1] + bias[col + 1];
            o.z = acc[i][j + 2] + bias[col + 2];
            o.w = acc[i][j + 3] + bias[col + 3];
            *(float4*)&C[(size_t)row * N + col] = o;
        }
    }
}

// ---------------- quaternion RoPE (in place) ------------------------------
__global__ void rope_kernel(float* __restrict__ q) {
    int idx = blockIdx.x * blockDim.x + threadIdx.x;   // B*S*H*G groups
    int g = idx & 15;
    int s = (idx >> 8) & 2047;

    float4 v = ((float4*)q)[idx];
    float ang = (float)s * powf(10000.0f, -(float)g / 16.0f);
    float cs = cosf(ang), sn = sinf(ang);
    int ax = g % 3;
    float ui = (ax == 0) ? sn : 0.f;
    float uj = (ax == 1) ? sn : 0.f;
    float uk = (ax == 2) ? sn : 0.f;
    float xr = v.x, xi = v.y, xj = v.z, xk = v.w;
    float4 o;
    o.x = cs * xr - ui * xi - uj * xj - uk * xk;
    o.y = cs * xi + ui * xr + uj * xk - uk * xj;
    o.z = cs * xj - ui * xk + uj * xr + uk * xi;
    o.w = cs * xk + ui * xj - uj * xi + uk * xr;
    ((float4*)q)[idx] = o;
}

// ---------------- causal flash attention (fp32) ---------------------------
// grid: (S/64, B*H). 64 threads, 1 query row each. K/V tiles 64x64 in smem.
__global__ __launch_bounds__(64) void attn_kernel(
    const float* __restrict__ Q, const float* __restrict__ K,
    const float* __restrict__ V, float* __restrict__ O) {
    __shared__ float Ks[64][64];
    __shared__ float Vs[64][64];
    __shared__ float Ss[64][65];

    int t  = threadIdx.x;
    int qt = blockIdx.x;
    int bh = blockIdx.y;
    int b  = bh / HQ, h = bh % HQ;
    int qrow = qt * 64 + t;

    const float* qptr = Q + (size_t)(b * SQ + qrow) * DIM + h * DH;
    float qreg[64];
    #pragma unroll
    for (int i = 0; i < 16; i++) {
        float4 v = ((const float4*)qptr)[i];
        qreg[4 * i + 0] = v.x; qreg[4 * i + 1] = v.y;
        qreg[4 * i + 2] = v.z; qreg[4 * i + 3] = v.w;
    }

    float o[64];
    #pragma unroll
    for (int d = 0; d < 64; d++) o[d] = 0.f;
    float mval = -1e30f, l = 0.f;

    for (int jt = 0; jt <= qt; jt++) {
        const float* kbase = K + (size_t)(b * SQ + jt * 64) * DIM + h * DH;
        const float* vbase = V + (size_t)(b * SQ + jt * 64) * DIM + h * DH;
        #pragma unroll
        for (int i = 0; i < 16; i++) {
            int fi  = t + 64 * i;       // 0..1023 float4s
            int row = fi >> 4;
            int c4  = fi & 15;
            ((float4*)Ks)[row * 16 + c4] = ((const float4*)(kbase + (size_t)row * DIM))[c4];
            ((float4*)Vs)[row * 16 + c4] = ((const float4*)(vbase + (size_t)row * DIM))[c4];
        }
        __syncthreads();

        float tmax = -1e30f;
        bool diag = (jt == qt);
        #pragma unroll 4
        for (int j = 0; j < 64; j++) {
            const float4* kr = (const float4*)Ks[j];
            float s = 0.f;
            #pragma unroll
            for (int d4 = 0; d4 < 16; d4++) {
                float4 kv = kr[d4];
                s += qreg[4 * d4 + 0] * kv.x + qreg[4 * d4 + 1] * kv.y
                   + qreg[4 * d4 + 2] * kv.z + qreg[4 * d4 + 3] * kv.w;
            }
            s *= 0.125f;                       // DH^-0.5
            if (diag && j > t) s = -1e30f;     // causal mask
            Ss[t][j] = s;
            tmax = fmaxf(tmax, s);
        }

        float mnew = fmaxf(mval, tmax);
        float corr = __expf(mval - mnew);
        l *= corr;
        #pragma unroll
        for (int d = 0; d < 64; d++) o[d] *= corr;

        #pragma unroll 2
        for (int j = 0; j < 64; j++) {
            float p = __expf(Ss[t][j] - mnew);
            l += p;
            const float4* vr = (const float4*)Vs[j];
            #pragma unroll
            for (int d4 = 0; d4 < 16; d4++) {
                float4 vv = vr[d4];
                o[4 * d4 + 0] += p * vv.x;
                o[4 * d4 + 1] += p * vv.y;
                o[4 * d4 + 2] += p * vv.z;
                o[4 * d4 + 3] += p * vv.w;
            }
        }
        mval = mnew;
        __syncthreads();
    }

    float inv = 1.f / l;
    float* optr = O + (size_t)(b * SQ + qrow) * DIM + h * DH;
    #pragma unroll
    for (int d4 = 0; d4 < 16; d4++) {
        float4 ov;
        ov.x = o[4 * d4 + 0] * inv; ov.y = o[4 * d4 + 1] * inv;
        ov.z = o[4 * d4 + 2] * inv; ov.w = o[4 * d4 + 3] * inv;
        ((float4*)optr)[d4] = ov;
    }
}

// ---------------- launch ---------------------------------------------------
extern "C" void kernel_launch(void* const* d_in, const int* in_sizes, int n_in,
                              void* d_out, int out_size) {
    const float* x = (const float*)d_in[0];
    // d_in[1] = mask (pure causal triu, ignored)
    const float* q_w[4] = {(const float*)d_in[2], (const float*)d_in[3],
                           (const float*)d_in[4], (const float*)d_in[5]};
    const float* q_b = (const float*)d_in[6];
    const float* k_w[4] = {(const float*)d_in[7], (const float*)d_in[8],
                           (const float*)d_in[9], (const float*)d_in[10]};
    const float* k_b = (const float*)d_in[11];
    const float* v_w[4] = {(const float*)d_in[12], (const float*)d_in[13],
                           (const float*)d_in[14], (const float*)d_in[15]};
    const float* v_b = (const float*)d_in[16];
    const float* o_w[4] = {(const float*)d_in[17], (const float*)d_in[18],
                           (const float*)d_in[19], (const float*)d_in[20]};
    const float* o_b = (const float*)d_in[21];

    float *wt, *qb, *kb, *vb, *ab;
    cudaGetSymbolAddress((void**)&wt, g_WT);
    cudaGetSymbolAddress((void**)&qb, g_q);
    cudaGetSymbolAddress((void**)&kb, g_k);
    cudaGetSymbolAddress((void**)&vb, g_v);
    cudaGetSymbolAddress((void**)&ab, g_attn);
    float* WTq = wt + 0 * (size_t)DIM * DIM;
    float* WTk = wt + 1 * (size_t)DIM * DIM;
    float* WTv = wt + 2 * (size_t)DIM * DIM;
    float* WTo = wt + 3 * (size_t)DIM * DIM;

    const int wthreads = 256;
    const int wblocks = (DIM * DIM) / wthreads;
    build_wt_kernel<<<wblocks, wthreads>>>(q_w[0], q_w[1], q_w[2], q_w[3], WTq);
    build_wt_kernel<<<wblocks, wthreads>>>(k_w[0], k_w[1], k_w[2], k_w[3], WTk);
    build_wt_kernel<<<wblocks, wthreads>>>(v_w[0], v_w[1], v_w[2], v_w[3], WTv);
    build_wt_kernel<<<wblocks, wthreads>>>(o_w[0], o_w[1], o_w[2], o_w[3], WTo);

    dim3 ggrid(DIM / BN, MROW / BM);   // (8, 32)
    sgemm_kernel<<<ggrid, 256>>>(x, WTq, q_b, qb);
    sgemm_kernel<<<ggrid, 256>>>(x, WTk, k_b, kb);
    sgemm_kernel<<<ggrid, 256>>>(x, WTv, v_b, vb);

    const int ngroups = BQ * SQ * HQ * GQ;     // 1M
    rope_kernel<<<ngroups / 256, 256>>>(qb);
    rope_kernel<<<ngroups / 256, 256>>>(kb);

    dim3 agrid(SQ / 64, BQ * HQ);              // (32, 32)
    attn_kernel<<<agrid, 64>>>(qb, kb, vb, ab);

    sgemm_kernel<<<ggrid, 256>>>(ab, WTo, o_b, (float*)d_out);
}

// round 4
// speedup vs baseline: 1.4186x; 1.4186x over previous
#include <cuda_runtime.h>
#include <cuda_bf16.h>
#include <math.h>
#include <cstdint>

#define BQ   2
#define SQ   2048
#define DIM  1024
#define HQ   16
#define DH   64
#define GQ   16
#define IQ   256
#define MROW (BQ*SQ)   /* 4096 */

// ---------------- device scratch (no allocations allowed) ----------------
__device__ float g_W[4][DIM*DIM];      // W_eff per projection, [n][k] layout (K-major rows)
__device__ float g_q[MROW*DIM];
__device__ float g_k[MROW*DIM];
__device__ float g_v[MROW*DIM];
__device__ float g_attn[MROW*DIM];

// ---------------- build effective quaternion weight [n][k] ----------------
// out[r, n] = sum_k x[r,k] * W[n,k];  W[n*DIM + k]
__global__ void build_w_kernel(const float* __restrict__ wr,
                               const float* __restrict__ wi,
                               const float* __restrict__ wj,
                               const float* __restrict__ wk,
                               float* __restrict__ W) {
    int idx = blockIdx.x * blockDim.x + threadIdx.x;   // 0 .. DIM*DIM-1
    int n = idx >> 10;
    int k = idx & 1023;
    int m = n >> 2, c = n & 3;
    int p = k >> 2, d = k & 3;

    const int   comp[4][4] = {{0,1,2,3},{1,0,2,3},{2,1,0,3},{3,1,2,0}};
    const float sgn [4][4] = {{ 1.f,-1.f,-1.f,-1.f},
                              { 1.f, 1.f,-1.f, 1.f},
                              { 1.f, 1.f, 1.f,-1.f},
                              { 1.f,-1.f, 1.f, 1.f}};
    const float* ws[4] = {wr, wi, wj, wk};
    W[idx] = sgn[c][d] * ws[comp[c][d]][m * IQ + p];
}

// ================= mma.sync bf16-split GEMM =================
// C[M,N] = A[M,K] @ W^T + bias, fp32 in/out, 2-way bf16 split, 3 products.
// Tile 128x128, 8 warps (2x4), warp tile 64x32, K-slab 32.
// smem per buffer (u32 units): AH@0, AL@2560, BH@5120, BL@7680; stride 20 u32/row.

__device__ __forceinline__ void split2(float x, float y, uint32_t& hi, uint32_t& lo) {
    uint32_t h;
    asm("cvt.rn.bf16x2.f32 %0, %1, %2;" : "=r"(h) : "f"(y), "f"(x));
    float xh = __uint_as_float(h << 16);
    float yh = __uint_as_float(h & 0xFFFF0000u);
    float xl = x - xh, yl = y - yh;
    uint32_t l;
    asm("cvt.rn.bf16x2.f32 %0, %1, %2;" : "=r"(l) : "f"(yl), "f"(xl));
    hi = h; lo = l;
}

__device__ __forceinline__ void mma16816(float* c, const uint32_t* a, const uint32_t* b) {
    asm volatile(
        "mma.sync.aligned.m16n8k16.row.col.f32.bf16.bf16.f32 "
        "{%0,%1,%2,%3}, {%4,%5,%6,%7}, {%8,%9}, {%0,%1,%2,%3};"
        : "+f"(c[0]), "+f"(c[1]), "+f"(c[2]), "+f"(c[3])
        : "r"(a[0]), "r"(a[1]), "r"(a[2]), "r"(a[3]), "r"(b[0]), "r"(b[1]));
}

#define SMS   20            /* u32 per smem row */
#define BUFU  10240         /* u32 per buffer   */
#define GEMM_SMEM (2 * BUFU * 4)

__global__ __launch_bounds__(256) void qgemm_mma(
    const float* __restrict__ A, const float* __restrict__ W,
    const float* __restrict__ bias, float* __restrict__ C) {
    extern __shared__ uint32_t smu[];
    const int tid  = threadIdx.x;
    const int lane = tid & 31, wid = tid >> 5;
    const int g = lane >> 2, t = lane & 3;
    const int wm = wid & 1, wn = wid >> 1;
    const int bm = blockIdx.y * 128, bn = blockIdx.x * 128;

    float acc[4][4][4];
    #pragma unroll
    for (int i = 0; i < 4; i++)
        #pragma unroll
        for (int j = 0; j < 4; j++)
            #pragma unroll
            for (int q = 0; q < 4; q++) acc[i][j][q] = 0.f;

    const int lrow = tid >> 3;      // 0..31 (+32*i)
    const int c4   = tid & 7;       // float4 index within 32-float slab
    const float* Aptr = A + (size_t)(bm + lrow) * DIM + c4 * 4;
    const float* Wptr = W + (size_t)(bn + lrow) * DIM + c4 * 4;
    const uint32_t sb = (uint32_t)(lrow * SMS + c4 * 2);

    // ---- prologue: slab 0 into buffer 0 ----
    {
        uint32_t* B0 = smu;
        #pragma unroll
        for (int i = 0; i < 4; i++) {
            float4 ra = *(const float4*)(Aptr + (size_t)i * 32 * DIM);
            float4 rb = *(const float4*)(Wptr + (size_t)i * 32 * DIM);
            uint32_t h0, l0, h1, l1;
            uint32_t off = sb + i * 32 * SMS;
            split2(ra.x, ra.y, h0, l0); split2(ra.z, ra.w, h1, l1);
            B0[off] = h0; B0[off + 1] = h1;
            B0[2560 + off] = l0; B0[2560 + off + 1] = l1;
            split2(rb.x, rb.y, h0, l0); split2(rb.z, rb.w, h1, l1);
            B0[5120 + off] = h0; B0[5120 + off + 1] = h1;
            B0[7680 + off] = l0; B0[7680 + off + 1] = l1;
        }
    }
    __syncthreads();

    for (int s = 0; s < 32; s++) {
        const int cb = s & 1, nb = (s + 1) & 1;
        float4 ra[4], rb[4];
        if (s + 1 < 32) {
            int k1 = (s + 1) * 32;
            #pragma unroll
            for (int i = 0; i < 4; i++) {
                ra[i] = *(const float4*)(Aptr + (size_t)i * 32 * DIM + k1);
                rb[i] = *(const float4*)(Wptr + (size_t)i * 32 * DIM + k1);
            }
        }

        // ---- compute slab s from buffer cb ----
        const uint32_t* base = smu + cb * BUFU;
        #pragma unroll
        for (int kk = 0; kk < 2; kk++) {
            uint32_t ah[4][4], al[4][4];
            #pragma unroll
            for (int mi = 0; mi < 4; mi++) {
                int r0 = (wm * 64 + mi * 16 + g) * SMS + kk * 8 + t;
                ah[mi][0] = base[r0];           ah[mi][1] = base[r0 + 8 * SMS];
                ah[mi][2] = base[r0 + 4];       ah[mi][3] = base[r0 + 8 * SMS + 4];
                al[mi][0] = base[2560 + r0];     al[mi][1] = base[2560 + r0 + 8 * SMS];
                al[mi][2] = base[2560 + r0 + 4]; al[mi][3] = base[2560 + r0 + 8 * SMS + 4];
            }
            uint32_t bh[4][2], bl[4][2];
            #pragma unroll
            for (int nj = 0; nj < 4; nj++) {
                int rn = (wn * 32 + nj * 8 + g) * SMS + kk * 8 + t;
                bh[nj][0] = base[5120 + rn]; bh[nj][1] = base[5120 + rn + 4];
                bl[nj][0] = base[7680 + rn]; bl[nj][1] = base[7680 + rn + 4];
            }
            #pragma unroll
            for (int mi = 0; mi < 4; mi++)
                #pragma unroll
                for (int nj = 0; nj < 4; nj++) {
                    mma16816(acc[mi][nj], ah[mi], bh[nj]);
                    mma16816(acc[mi][nj], ah[mi], bl[nj]);
                    mma16816(acc[mi][nj], al[mi], bh[nj]);
                }
        }

        if (s + 1 < 32) {
            uint32_t* BN = smu + nb * BUFU;
            #pragma unroll
            for (int i = 0; i < 4; i++) {
                uint32_t h0, l0, h1, l1;
                uint32_t off = sb + i * 32 * SMS;
                split2(ra[i].x, ra[i].y, h0, l0); split2(ra[i].z, ra[i].w, h1, l1);
                BN[off] = h0; BN[off + 1] = h1;
                BN[2560 + off] = l0; BN[2560 + off + 1] = l1;
                split2(rb[i].x, rb[i].y, h0, l0); split2(rb[i].z, rb[i].w, h1, l1);
                BN[5120 + off] = h0; BN[5120 + off + 1] = h1;
                BN[7680 + off] = l0; BN[7680 + off + 1] = l1;
            }
        }
        __syncthreads();
    }

    // ---- epilogue ----
    #pragma unroll
    for (int mi = 0; mi < 4; mi++) {
        int row = bm + wm * 64 + mi * 16 + g;
        #pragma unroll
        for (int nj = 0; nj < 4; nj++) {
            int col = bn + wn * 32 + nj * 8 + 2 * t;
            float bx = bias[col], by = bias[col + 1];
            float2 v;
            v.x = acc[mi][nj][0] + bx; v.y = acc[mi][nj][1] + by;
            *(float2*)&C[(size_t)row * DIM + col] = v;
            v.x = acc[mi][nj][2] + bx; v.y = acc[mi][nj][3] + by;
            *(float2*)&C[(size_t)(row + 8) * DIM + col] = v;
        }
    }
}

// ---------------- quaternion RoPE (in place) ------------------------------
__global__ void rope_kernel(float* __restrict__ q) {
    int idx = blockIdx.x * blockDim.x + threadIdx.x;   // B*S*H*G groups
    int g = idx & 15;
    int s = (idx >> 8) & 2047;

    float4 v = ((float4*)q)[idx];
    float ang = (float)s * powf(10000.0f, -(float)g / 16.0f);
    float cs = cosf(ang), sn = sinf(ang);
    int ax = g % 3;
    float ui = (ax == 0) ? sn : 0.f;
    float uj = (ax == 1) ? sn : 0.f;
    float uk = (ax == 2) ? sn : 0.f;
    float xr = v.x, xi = v.y, xj = v.z, xk = v.w;
    float4 o;
    o.x = cs * xr - ui * xi - uj * xj - uk * xk;
    o.y = cs * xi + ui * xr + uj * xk - uk * xj;
    o.z = cs * xj - ui * xk + uj * xr + uk * xi;
    o.w = cs * xk + ui * xj - uj * xi + uk * xr;
    ((float4*)q)[idx] = o;
}

// ---------------- causal flash attention (fp32) ---------------------------
__global__ __launch_bounds__(64) void attn_kernel(
    const float* __restrict__ Q, const float* __restrict__ K,
    const float* __restrict__ V, float* __restrict__ O) {
    __shared__ float Ks[64][64];
    __shared__ float Vs[64][64];
    __shared__ float Ss[64][65];

    int t  = threadIdx.x;
    int qt = blockIdx.x;
    int bh = blockIdx.y;
    int b  = bh / HQ, h = bh % HQ;
    int qrow = qt * 64 + t;

    const float* qptr = Q + (size_t)(b * SQ + qrow) * DIM + h * DH;
    float qreg[64];
    #pragma unroll
    for (int i = 0; i < 16; i++) {
        float4 v = ((const float4*)qptr)[i];
        qreg[4 * i + 0] = v.x; qreg[4 * i + 1] = v.y;
        qreg[4 * i + 2] = v.z; qreg[4 * i + 3] = v.w;
    }

    float o[64];
    #pragma unroll
    for (int d = 0; d < 64; d++) o[d] = 0.f;
    float mval = -1e30f, l = 0.f;

    for (int jt = 0; jt <= qt; jt++) {
        const float* kbase = K + (size_t)(b * SQ + jt * 64) * DIM + h * DH;
        const float* vbase = V + (size_t)(b * SQ + jt * 64) * DIM + h * DH;
        #pragma unroll
        for (int i = 0; i < 16; i++) {
            int fi  = t + 64 * i;
            int row = fi >> 4;
            int cc  = fi & 15;
            ((float4*)Ks)[row * 16 + cc] = ((const float4*)(kbase + (size_t)row * DIM))[cc];
            ((float4*)Vs)[row * 16 + cc] = ((const float4*)(vbase + (size_t)row * DIM))[cc];
        }
        __syncthreads();

        float tmax = -1e30f;
        bool diag = (jt == qt);
        #pragma unroll 4
        for (int j = 0; j < 64; j++) {
            const float4* kr = (const float4*)Ks[j];
            float s = 0.f;
            #pragma unroll
            for (int d4 = 0; d4 < 16; d4++) {
                float4 kv = kr[d4];
                s += qreg[4 * d4 + 0] * kv.x + qreg[4 * d4 + 1] * kv.y
                   + qreg[4 * d4 + 2] * kv.z + qreg[4 * d4 + 3] * kv.w;
            }
            s *= 0.125f;
            if (diag && j > t) s = -1e30f;
            Ss[t][j] = s;
            tmax = fmaxf(tmax, s);
        }

        float mnew = fmaxf(mval, tmax);
        float corr = __expf(mval - mnew);
        l *= corr;
        #pragma unroll
        for (int d = 0; d < 64; d++) o[d] *= corr;

        #pragma unroll 2
        for (int j = 0; j < 64; j++) {
            float p = __expf(Ss[t][j] - mnew);
            l += p;
            const float4* vr = (const float4*)Vs[j];
            #pragma unroll
            for (int d4 = 0; d4 < 16; d4++) {
                float4 vv = vr[d4];
                o[4 * d4 + 0] += p * vv.x;
                o[4 * d4 + 1] += p * vv.y;
                o[4 * d4 + 2] += p * vv.z;
                o[4 * d4 + 3] += p * vv.w;
            }
        }
        mval = mnew;
        __syncthreads();
    }

    float inv = 1.f / l;
    float* optr = O + (size_t)(b * SQ + qrow) * DIM + h * DH;
    #pragma unroll
    for (int d4 = 0; d4 < 16; d4++) {
        float4 ov;
        ov.x = o[4 * d4 + 0] * inv; ov.y = o[4 * d4 + 1] * inv;
        ov.z = o[4 * d4 + 2] * inv; ov.w = o[4 * d4 + 3] * inv;
        ((float4*)optr)[d4] = ov;
    }
}

// ---------------- launch ---------------------------------------------------
extern "C" void kernel_launch(void* const* d_in, const int* in_sizes, int n_in,
                              void* d_out, int out_size) {
    const float* x = (const float*)d_in[0];
    // d_in[1] = mask (pure causal triu, ignored)
    const float* q_w[4] = {(const float*)d_in[2], (const float*)d_in[3],
                           (const float*)d_in[4], (const float*)d_in[5]};
    const float* q_b = (const float*)d_in[6];
    const float* k_w[4] = {(const float*)d_in[7], (const float*)d_in[8],
                           (const float*)d_in[9], (const float*)d_in[10]};
    const float* k_b = (const float*)d_in[11];
    const float* v_w[4] = {(const float*)d_in[12], (const float*)d_in[13],
                           (const float*)d_in[14], (const float*)d_in[15]};
    const float* v_b = (const float*)d_in[16];
    const float* o_w[4] = {(const float*)d_in[17], (const float*)d_in[18],
                           (const float*)d_in[19], (const float*)d_in[20]};
    const float* o_b = (const float*)d_in[21];

    float *wt, *qb, *kb, *vb, *ab;
    cudaGetSymbolAddress((void**)&wt, g_W);
    cudaGetSymbolAddress((void**)&qb, g_q);
    cudaGetSymbolAddress((void**)&kb, g_k);
    cudaGetSymbolAddress((void**)&vb, g_v);
    cudaGetSymbolAddress((void**)&ab, g_attn);
    float* Wq = wt + 0 * (size_t)DIM * DIM;
    float* Wk = wt + 1 * (size_t)DIM * DIM;
    float* Wv = wt + 2 * (size_t)DIM * DIM;
    float* Wo = wt + 3 * (size_t)DIM * DIM;

    cudaFuncSetAttribute(qgemm_mma, cudaFuncAttributeMaxDynamicSharedMemorySize,
                         GEMM_SMEM);

    const int wthreads = 256;
    const int wblocks = (DIM * DIM) / wthreads;
    build_w_kernel<<<wblocks, wthreads>>>(q_w[0], q_w[1], q_w[2], q_w[3], Wq);
    build_w_kernel<<<wblocks, wthreads>>>(k_w[0], k_w[1], k_w[2], k_w[3], Wk);
    build_w_kernel<<<wblocks, wthreads>>>(v_w[0], v_w[1], v_w[2], v_w[3], Wv);
    build_w_kernel<<<wblocks, wthreads>>>(o_w[0], o_w[1], o_w[2], o_w[3], Wo);

    dim3 ggrid(DIM / 128, MROW / 128);   // (8, 32)
    qgemm_mma<<<ggrid, 256, GEMM_SMEM>>>(x, Wq, q_b, qb);
    qgemm_mma<<<ggrid, 256, GEMM_SMEM>>>(x, Wk, k_b, kb);
    qgemm_mma<<<ggrid, 256, GEMM_SMEM>>>(x, Wv, v_b, vb);

    const int ngroups = BQ * SQ * HQ * GQ;     // 1M
    rope_kernel<<<ngroups / 256, 256>>>(qb);
    rope_kernel<<<ngroups / 256, 256>>>(kb);

    dim3 agrid(SQ / 64, BQ * HQ);              // (32, 32)
    attn_kernel<<<agrid, 64>>>(qb, kb, vb, ab);

    qgemm_mma<<<ggrid, 256, GEMM_SMEM>>>(ab, Wo, o_b, (float*)d_out);
}

// round 5
// speedup vs baseline: 1.4335x; 1.0105x over previous
#include <cuda_runtime.h>
#include <cuda_bf16.h>
#include <math.h>
#include <cstdint>

#define BQ   2
#define SQ   2048
#define DIM  1024
#define HQ   16
#define DH   64
#define GQ   16
#define IQ   256
#define MROW (BQ*SQ)   /* 4096 */

// ---------------- device scratch (no allocations allowed) ----------------
__device__ __nv_bfloat16 g_wh[4][DIM*DIM];   // W_eff hi, [n][k]
__device__ __nv_bfloat16 g_wl[4][DIM*DIM];   // W_eff lo
__device__ __nv_bfloat16 g_ah[MROW*DIM];     // activation hi (x, later attn out)
__device__ __nv_bfloat16 g_al[MROW*DIM];     // activation lo
__device__ float g_q[MROW*DIM];
__device__ float g_k[MROW*DIM];
__device__ float g_v[MROW*DIM];
__device__ float g_attn[MROW*DIM];

// ---------------- helpers --------------------------------------------------
__device__ __forceinline__ uint32_t smem_to_u32(const void* p) {
    uint32_t a;
    asm("{ .reg .u64 t; cvta.to.shared.u64 t, %1; cvt.u32.u64 %0, t; }"
        : "=r"(a) : "l"(p));
    return a;
}
__device__ __forceinline__ void cp_async16(uint32_t dst, const void* src) {
    asm volatile("cp.async.ca.shared.global [%0], [%1], 16;"
                 :: "r"(dst), "l"(src));
}
#define CP_COMMIT() asm volatile("cp.async.commit_group;" ::: "memory")
#define CP_WAIT(n)  asm volatile("cp.async.wait_group %0;" :: "n"(n) : "memory")

// split fp32 pair into bf16x2 hi (packed y|x) and lo
__device__ __forceinline__ void split2(float x, float y, uint32_t& hi, uint32_t& lo) {
    uint32_t h;
    asm("cvt.rn.bf16x2.f32 %0, %1, %2;" : "=r"(h) : "f"(y), "f"(x));
    float xh = __uint_as_float(h << 16);
    float yh = __uint_as_float(h & 0xFFFF0000u);
    float xl = x - xh, yl = y - yh;
    uint32_t l;
    asm("cvt.rn.bf16x2.f32 %0, %1, %2;" : "=r"(l) : "f"(yl), "f"(xl));
    hi = h; lo = l;
}

__device__ __forceinline__ void mma16816(float* c, const uint32_t* a, const uint32_t* b) {
    asm volatile(
        "mma.sync.aligned.m16n8k16.row.col.f32.bf16.bf16.f32 "
        "{%0,%1,%2,%3}, {%4,%5,%6,%7}, {%8,%9}, {%0,%1,%2,%3};"
        : "+f"(c[0]), "+f"(c[1]), "+f"(c[2]), "+f"(c[3])
        : "r"(a[0]), "r"(a[1]), "r"(a[2]), "r"(a[3]), "r"(b[0]), "r"(b[1]));
}

// ---------------- build effective quaternion weight, split to bf16 --------
// W_eff[n][k]: n = 4m+c (out), k = 4p+d (in)
__global__ void build_w_split_kernel(const float* __restrict__ wr,
                                     const float* __restrict__ wi,
                                     const float* __restrict__ wj,
                                     const float* __restrict__ wk,
                                     __nv_bfloat16* __restrict__ Wh,
                                     __nv_bfloat16* __restrict__ Wl) {
    int idx = blockIdx.x * blockDim.x + threadIdx.x;   // 0 .. DIM*DIM/2-1
    int n  = idx >> 9;
    int k2 = (idx & 511) * 2;

    const int   comp[4][4] = {{0,1,2,3},{1,0,2,3},{2,1,0,3},{3,1,2,0}};
    const float sgn [4][4] = {{ 1.f,-1.f,-1.f,-1.f},
                              { 1.f, 1.f,-1.f, 1.f},
                              { 1.f, 1.f, 1.f,-1.f},
                              { 1.f,-1.f, 1.f, 1.f}};
    const float* ws[4] = {wr, wi, wj, wk};
    int m = n >> 2, c = n & 3;

    int p0 = k2 >> 2, d0 = k2 & 3;
    int k1 = k2 + 1;
    int p1 = k1 >> 2, d1 = k1 & 3;
    float v0 = sgn[c][d0] * ws[comp[c][d0]][m * IQ + p0];
    float v1 = sgn[c][d1] * ws[comp[c][d1]][m * IQ + p1];

    uint32_t h, l;
    split2(v0, v1, h, l);
    ((uint32_t*)Wh)[idx] = h;
    ((uint32_t*)Wl)[idx] = l;
}

// ---------------- split fp32 activation into bf16 hi/lo --------------------
__global__ void split_kernel(const float* __restrict__ in,
                             __nv_bfloat16* __restrict__ hi,
                             __nv_bfloat16* __restrict__ lo) {
    int i = blockIdx.x * blockDim.x + threadIdx.x;     // float4 index
    float4 v = ((const float4*)in)[i];
    uint32_t h0, l0, h1, l1;
    split2(v.x, v.y, h0, l0);
    split2(v.z, v.w, h1, l1);
    ((uint2*)hi)[i] = make_uint2(h0, h1);
    ((uint2*)lo)[i] = make_uint2(l0, l1);
}

// ================= mma.sync bf16-split GEMM (pre-split inputs) =============
// C[M,N] = (Ah+Al)[M,K] @ (Bh+Bl)^T[N,K] + bias, 3 products.
// Tile 128x128, 8 warps (2x4), warp tile 64x32, K-slab 32, cp.async double buf.
// smem per buffer (u32 units): AH@0, AL@2560, BH@5120, BL@7680; row stride 20 u32.
#define SMS   20
#define BUFU  10240
#define GEMM_SMEM (2 * BUFU * 4)

__global__ __launch_bounds__(256) void qgemm_bf16(
    const __nv_bfloat16* __restrict__ Ah, const __nv_bfloat16* __restrict__ Al,
    const __nv_bfloat16* __restrict__ Bh, const __nv_bfloat16* __restrict__ Bl,
    const float* __restrict__ bias, float* __restrict__ C) {
    extern __shared__ uint32_t smu[];
    const uint32_t sbase = smem_to_u32(smu);
    const int tid  = threadIdx.x;
    const int lane = tid & 31, wid = tid >> 5;
    const int g = lane >> 2, t = lane & 3;
    const int wm = wid & 1, wn = wid >> 1;
    const int bm = blockIdx.y * 128, bn = blockIdx.x * 128;

    float acc[4][4][4];
    #pragma unroll
    for (int i = 0; i < 4; i++)
        #pragma unroll
        for (int j = 0; j < 4; j++)
            #pragma unroll
            for (int q = 0; q < 4; q++) acc[i][j][q] = 0.f;

    // cp.async slab loader: each thread moves 2 x 16B chunks per matrix half
    const int crow0 = tid >> 2;          // 0..63
    const int ccol  = tid & 3;           // 16B chunk within 64B row
    const __nv_bfloat16* pAh = Ah + (size_t)(bm + crow0) * DIM + ccol * 8;
    const __nv_bfloat16* pAl = Al + (size_t)(bm + crow0) * DIM + ccol * 8;
    const __nv_bfloat16* pBh = Bh + (size_t)(bn + crow0) * DIM + ccol * 8;
    const __nv_bfloat16* pBl = Bl + (size_t)(bn + crow0) * DIM + ccol * 8;
    const uint32_t doff0 = (uint32_t)(crow0 * SMS + ccol * 4) * 4;
    const uint32_t rstep = (uint32_t)(64 * SMS) * 4;   // +64 rows in smem bytes

    #define ISSUE_SLAB(s, b) do {                                              \
        int _k0 = (s) * 32;                                                    \
        uint32_t _d = sbase + (uint32_t)(b) * (BUFU * 4) + doff0;              \
        cp_async16(_d,                 pAh + _k0);                             \
        cp_async16(_d + rstep,         pAh + _k0 + (size_t)64 * DIM);          \
        cp_async16(_d + 2560*4,         pAl + _k0);                            \
        cp_async16(_d + 2560*4 + rstep, pAl + _k0 + (size_t)64 * DIM);         \
        cp_async16(_d + 5120*4,         pBh + _k0);                            \
        cp_async16(_d + 5120*4 + rstep, pBh + _k0 + (size_t)64 * DIM);         \
        cp_async16(_d + 7680*4,         pBl + _k0);                            \
        cp_async16(_d + 7680*4 + rstep, pBl + _k0 + (size_t)64 * DIM);         \
        CP_COMMIT();                                                           \
    } while (0)

    ISSUE_SLAB(0, 0);

    for (int s = 0; s < 32; s++) {
        const int cb = s & 1, nb = cb ^ 1;
        if (s + 1 < 32) {
            ISSUE_SLAB(s + 1, nb);
            CP_WAIT(1);
        } else {
            CP_WAIT(0);
        }
        __syncthreads();

        const uint32_t* base = smu + cb * BUFU;
        #pragma unroll
        for (int kk = 0; kk < 2; kk++) {
            uint32_t ah[4][4], al[4][4];
            #pragma unroll
            for (int mi = 0; mi < 4; mi++) {
                int r0 = (wm * 64 + mi * 16 + g) * SMS + kk * 8 + t;
                ah[mi][0] = base[r0];            ah[mi][1] = base[r0 + 8 * SMS];
                ah[mi][2] = base[r0 + 4];        ah[mi][3] = base[r0 + 8 * SMS + 4];
                al[mi][0] = base[2560 + r0];     al[mi][1] = base[2560 + r0 + 8 * SMS];
                al[mi][2] = base[2560 + r0 + 4]; al[mi][3] = base[2560 + r0 + 8 * SMS + 4];
            }
            uint32_t bh[4][2], bl[4][2];
            #pragma unroll
            for (int nj = 0; nj < 4; nj++) {
                int rn = (wn * 32 + nj * 8 + g) * SMS + kk * 8 + t;
                bh[nj][0] = base[5120 + rn]; bh[nj][1] = base[5120 + rn + 4];
                bl[nj][0] = base[7680 + rn]; bl[nj][1] = base[7680 + rn + 4];
            }
            #pragma unroll
            for (int mi = 0; mi < 4; mi++)
                #pragma unroll
                for (int nj = 0; nj < 4; nj++) {
                    mma16816(acc[mi][nj], ah[mi], bh[nj]);
                    mma16816(acc[mi][nj], ah[mi], bl[nj]);
                    mma16816(acc[mi][nj], al[mi], bh[nj]);
                }
        }
        __syncthreads();
    }

    // ---- epilogue ----
    #pragma unroll
    for (int mi = 0; mi < 4; mi++) {
        int row = bm + wm * 64 + mi * 16 + g;
        #pragma unroll
        for (int nj = 0; nj < 4; nj++) {
            int col = bn + wn * 32 + nj * 8 + 2 * t;
            float bx = bias[col], by = bias[col + 1];
            float2 v;
            v.x = acc[mi][nj][0] + bx; v.y = acc[mi][nj][1] + by;
            *(float2*)&C[(size_t)row * DIM + col] = v;
            v.x = acc[mi][nj][2] + bx; v.y = acc[mi][nj][3] + by;
            *(float2*)&C[(size_t)(row + 8) * DIM + col] = v;
        }
    }
}

// ---------------- quaternion RoPE (in place) ------------------------------
__global__ void rope_kernel(float* __restrict__ q) {
    int idx = blockIdx.x * blockDim.x + threadIdx.x;
    int g = idx & 15;
    int s = (idx >> 8) & 2047;

    float4 v = ((float4*)q)[idx];
    float ang = (float)s * powf(10000.0f, -(float)g / 16.0f);
    float cs = cosf(ang), sn = sinf(ang);
    int ax = g % 3;
    float ui = (ax == 0) ? sn : 0.f;
    float uj = (ax == 1) ? sn : 0.f;
    float uk = (ax == 2) ? sn : 0.f;
    float xr = v.x, xi = v.y, xj = v.z, xk = v.w;
    float4 o;
    o.x = cs * xr - ui * xi - uj * xj - uk * xk;
    o.y = cs * xi + ui * xr + uj * xk - uk * xj;
    o.z = cs * xj - ui * xk + uj * xr + uk * xi;
    o.w = cs * xk + ui * xj - uj * xi + uk * xr;
    ((float4*)q)[idx] = o;
}

// ---------------- causal flash attention (fp32) ---------------------------
__global__ __launch_bounds__(64) void attn_kernel(
    const float* __restrict__ Q, const float* __restrict__ K,
    const float* __restrict__ V, float* __restrict__ O) {
    __shared__ float Ks[64][64];
    __shared__ float Vs[64][64];
    __shared__ float Ss[64][65];

    int t  = threadIdx.x;
    int qt = blockIdx.x;
    int bh = blockIdx.y;
    int b  = bh / HQ, h = bh % HQ;
    int qrow = qt * 64 + t;

    const float* qptr = Q + (size_t)(b * SQ + qrow) * DIM + h * DH;
    float qreg[64];
    #pragma unroll
    for (int i = 0; i < 16; i++) {
        float4 v = ((const float4*)qptr)[i];
        qreg[4 * i + 0] = v.x; qreg[4 * i + 1] = v.y;
        qreg[4 * i + 2] = v.z; qreg[4 * i + 3] = v.w;
    }

    float o[64];
    #pragma unroll
    for (int d = 0; d < 64; d++) o[d] = 0.f;
    float mval = -1e30f, l = 0.f;

    for (int jt = 0; jt <= qt; jt++) {
        const float* kbase = K + (size_t)(b * SQ + jt * 64) * DIM + h * DH;
        const float* vbase = V + (size_t)(b * SQ + jt * 64) * DIM + h * DH;
        #pragma unroll
        for (int i = 0; i < 16; i++) {
            int fi  = t + 64 * i;
            int row = fi >> 4;
            int cc  = fi & 15;
            ((float4*)Ks)[row * 16 + cc] = ((const float4*)(kbase + (size_t)row * DIM))[cc];
            ((float4*)Vs)[row * 16 + cc] = ((const float4*)(vbase + (size_t)row * DIM))[cc];
        }
        __syncthreads();

        float tmax = -1e30f;
        bool diag = (jt == qt);
        #pragma unroll 4
        for (int j = 0; j < 64; j++) {
            const float4* kr = (const float4*)Ks[j];
            float s = 0.f;
            #pragma unroll
            for (int d4 = 0; d4 < 16; d4++) {
                float4 kv = kr[d4];
                s += qreg[4 * d4 + 0] * kv.x + qreg[4 * d4 + 1] * kv.y
                   + qreg[4 * d4 + 2] * kv.z + qreg[4 * d4 + 3] * kv.w;
            }
            s *= 0.125f;
            if (diag && j > t) s = -1e30f;
            Ss[t][j] = s;
            tmax = fmaxf(tmax, s);
        }

        float mnew = fmaxf(mval, tmax);
        float corr = __expf(mval - mnew);
        l *= corr;
        #pragma unroll
        for (int d = 0; d < 64; d++) o[d] *= corr;

        #pragma unroll 2
        for (int j = 0; j < 64; j++) {
            float p = __expf(Ss[t][j] - mnew);
            l += p;
            const float4* vr = (const float4*)Vs[j];
            #pragma unroll
            for (int d4 = 0; d4 < 16; d4++) {
                float4 vv = vr[d4];
                o[4 * d4 + 0] += p * vv.x;
                o[4 * d4 + 1] += p * vv.y;
                o[4 * d4 + 2] += p * vv.z;
                o[4 * d4 + 3] += p * vv.w;
            }
        }
        mval = mnew;
        __syncthreads();
    }

    float inv = 1.f / l;
    float* optr = O + (size_t)(b * SQ + qrow) * DIM + h * DH;
    #pragma unroll
    for (int d4 = 0; d4 < 16; d4++) {
        float4 ov;
        ov.x = o[4 * d4 + 0] * inv; ov.y = o[4 * d4 + 1] * inv;
        ov.z = o[4 * d4 + 2] * inv; ov.w = o[4 * d4 + 3] * inv;
        ((float4*)optr)[d4] = ov;
    }
}

// ---------------- launch ---------------------------------------------------
extern "C" void kernel_launch(void* const* d_in, const int* in_sizes, int n_in,
                              void* d_out, int out_size) {
    const float* x = (const float*)d_in[0];
    // d_in[1] = mask (pure causal triu, ignored)
    const float* q_w[4] = {(const float*)d_in[2], (const float*)d_in[3],
                           (const float*)d_in[4], (const float*)d_in[5]};
    const float* q_b = (const float*)d_in[6];
    const float* k_w[4] = {(const float*)d_in[7], (const float*)d_in[8],
                           (const float*)d_in[9], (const float*)d_in[10]};
    const float* k_b = (const float*)d_in[11];
    const float* v_w[4] = {(const float*)d_in[12], (const float*)d_in[13],
                           (const float*)d_in[14], (const float*)d_in[15]};
    const float* v_b = (const float*)d_in[16];
    const float* o_w[4] = {(const float*)d_in[17], (const float*)d_in[18],
                           (const float*)d_in[19], (const float*)d_in[20]};
    const float* o_b = (const float*)d_in[21];

    __nv_bfloat16 *wh, *wl, *ah, *al;
    float *qb, *kb, *vb, *ab;
    cudaGetSymbolAddress((void**)&wh, g_wh);
    cudaGetSymbolAddress((void**)&wl, g_wl);
    cudaGetSymbolAddress((void**)&ah, g_ah);
    cudaGetSymbolAddress((void**)&al, g_al);
    cudaGetSymbolAddress((void**)&qb, g_q);
    cudaGetSymbolAddress((void**)&kb, g_k);
    cudaGetSymbolAddress((void**)&vb, g_v);
    cudaGetSymbolAddress((void**)&ab, g_attn);

    __nv_bfloat16* Wh[4];
    __nv_bfloat16* Wl[4];
    for (int i = 0; i < 4; i++) {
        Wh[i] = wh + (size_t)i * DIM * DIM;
        Wl[i] = wl + (size_t)i * DIM * DIM;
    }

    cudaFuncSetAttribute(qgemm_bf16, cudaFuncAttributeMaxDynamicSharedMemorySize,
                         GEMM_SMEM);

    const int wblocks = (DIM * DIM / 2) / 256;
    build_w_split_kernel<<<wblocks, 256>>>(q_w[0], q_w[1], q_w[2], q_w[3], Wh[0], Wl[0]);
    build_w_split_kernel<<<wblocks, 256>>>(k_w[0], k_w[1], k_w[2], k_w[3], Wh[1], Wl[1]);
    build_w_split_kernel<<<wblocks, 256>>>(v_w[0], v_w[1], v_w[2], v_w[3], Wh[2], Wl[2]);
    build_w_split_kernel<<<wblocks, 256>>>(o_w[0], o_w[1], o_w[2], o_w[3], Wh[3], Wl[3]);

    const int sblocks = (MROW * DIM / 4) / 256;
    split_kernel<<<sblocks, 256>>>(x, ah, al);

    dim3 ggrid(DIM / 128, MROW / 128);   // (8, 32)
    qgemm_bf16<<<ggrid, 256, GEMM_SMEM>>>(ah, al, Wh[0], Wl[0], q_b, qb);
    qgemm_bf16<<<ggrid, 256, GEMM_SMEM>>>(ah, al, Wh[1], Wl[1], k_b, kb);
    qgemm_bf16<<<ggrid, 256, GEMM_SMEM>>>(ah, al, Wh[2], Wl[2], v_b, vb);

    const int ngroups = BQ * SQ * HQ * GQ;     // 1M
    rope_kernel<<<ngroups / 256, 256>>>(qb);
    rope_kernel<<<ngroups / 256, 256>>>(kb);

    dim3 agrid(SQ / 64, BQ * HQ);              // (32, 32)
    attn_kernel<<<agrid, 64>>>(qb, kb, vb, ab);

    // reuse activation split buffers for the attention output
    split_kernel<<<sblocks, 256>>>(ab, ah, al);
    qgemm_bf16<<<ggrid, 256, GEMM_SMEM>>>(ah, al, Wh[3], Wl[3], o_b, (float*)d_out);
}

// round 6
// speedup vs baseline: 2.6991x; 1.8829x over previous
#include <cuda_runtime.h>
#include <cuda_bf16.h>
#include <math.h>
#include <cstdint>

#define BQ   2
#define SQ   2048
#define DIM  1024
#define HQ   16
#define DH   64
#define GQ   16
#define IQ   256
#define MROW (BQ*SQ)   /* 4096 */

// ---------------- device scratch (no allocations allowed) ----------------
__device__ __nv_bfloat16 g_wh[4][DIM*DIM];   // W_eff hi, [n][k]
__device__ __nv_bfloat16 g_wl[4][DIM*DIM];   // W_eff lo
__device__ __nv_bfloat16 g_ah[MROW*DIM];     // activation hi (x, later attn out)
__device__ __nv_bfloat16 g_al[MROW*DIM];     // activation lo
__device__ __nv_bfloat16 g_qh[MROW*DIM];
__device__ __nv_bfloat16 g_ql[MROW*DIM];
__device__ __nv_bfloat16 g_kh[MROW*DIM];
__device__ __nv_bfloat16 g_kl[MROW*DIM];
__device__ __nv_bfloat16 g_vh[MROW*DIM];
__device__ __nv_bfloat16 g_vl[MROW*DIM];
__device__ float g_q[MROW*DIM];
__device__ float g_k[MROW*DIM];
__device__ float g_v[MROW*DIM];
__device__ float g_attn[MROW*DIM];

// ---------------- helpers --------------------------------------------------
__device__ __forceinline__ uint32_t smem_to_u32(const void* p) {
    uint32_t a;
    asm("{ .reg .u64 t; cvta.to.shared.u64 t, %1; cvt.u32.u64 %0, t; }"
        : "=r"(a) : "l"(p));
    return a;
}
__device__ __forceinline__ void cp_async16(uint32_t dst, const void* src) {
    asm volatile("cp.async.ca.shared.global [%0], [%1], 16;"
                 :: "r"(dst), "l"(src));
}
#define CP_COMMIT() asm volatile("cp.async.commit_group;" ::: "memory")
#define CP_WAIT(n)  asm volatile("cp.async.wait_group %0;" :: "n"(n) : "memory")

// split fp32 pair into bf16x2 hi (x low, y high) and lo
__device__ __forceinline__ void split2(float x, float y, uint32_t& hi, uint32_t& lo) {
    uint32_t h;
    asm("cvt.rn.bf16x2.f32 %0, %1, %2;" : "=r"(h) : "f"(y), "f"(x));
    float xh = __uint_as_float(h << 16);
    float yh = __uint_as_float(h & 0xFFFF0000u);
    float xl = x - xh, yl = y - yh;
    uint32_t l;
    asm("cvt.rn.bf16x2.f32 %0, %1, %2;" : "=r"(l) : "f"(yl), "f"(xl));
    hi = h; lo = l;
}

__device__ __forceinline__ void mma16816(float* c, const uint32_t* a, const uint32_t* b) {
    asm volatile(
        "mma.sync.aligned.m16n8k16.row.col.f32.bf16.bf16.f32 "
        "{%0,%1,%2,%3}, {%4,%5,%6,%7}, {%8,%9}, {%0,%1,%2,%3};"
        : "+f"(c[0]), "+f"(c[1]), "+f"(c[2]), "+f"(c[3])
        : "r"(a[0]), "r"(a[1]), "r"(a[2]), "r"(a[3]), "r"(b[0]), "r"(b[1]));
}
__device__ __forceinline__ void ldmatrix_x4(uint32_t* r, uint32_t addr) {
    asm volatile("ldmatrix.sync.aligned.m8n8.x4.shared.b16 {%0,%1,%2,%3}, [%4];"
                 : "=r"(r[0]), "=r"(r[1]), "=r"(r[2]), "=r"(r[3]) : "r"(addr));
}
__device__ __forceinline__ void ldmatrix_x2(uint32_t* r, uint32_t addr) {
    asm volatile("ldmatrix.sync.aligned.m8n8.x2.shared.b16 {%0,%1}, [%2];"
                 : "=r"(r[0]), "=r"(r[1]) : "r"(addr));
}
__device__ __forceinline__ void ldmatrix_x2_trans(uint32_t* r, uint32_t addr) {
    asm volatile("ldmatrix.sync.aligned.m8n8.x2.trans.shared.b16 {%0,%1}, [%2];"
                 : "=r"(r[0]), "=r"(r[1]) : "r"(addr));
}

// ---------------- build effective quaternion weight, split to bf16 --------
__global__ void build_w_split_kernel(const float* __restrict__ wr,
                                     const float* __restrict__ wi,
                                     const float* __restrict__ wj,
                                     const float* __restrict__ wk,
                                     __nv_bfloat16* __restrict__ Wh,
                                     __nv_bfloat16* __restrict__ Wl) {
    int idx = blockIdx.x * blockDim.x + threadIdx.x;   // 0 .. DIM*DIM/2-1
    int n  = idx >> 9;
    int k2 = (idx & 511) * 2;

    const int   comp[4][4] = {{0,1,2,3},{1,0,2,3},{2,1,0,3},{3,1,2,0}};
    const float sgn [4][4] = {{ 1.f,-1.f,-1.f,-1.f},
                              { 1.f, 1.f,-1.f, 1.f},
                              { 1.f, 1.f, 1.f,-1.f},
                              { 1.f,-1.f, 1.f, 1.f}};
    const float* ws[4] = {wr, wi, wj, wk};
    int m = n >> 2, c = n & 3;

    int p0 = k2 >> 2, d0 = k2 & 3;
    int k1 = k2 + 1;
    int p1 = k1 >> 2, d1 = k1 & 3;
    float v0 = sgn[c][d0] * ws[comp[c][d0]][m * IQ + p0];
    float v1 = sgn[c][d1] * ws[comp[c][d1]][m * IQ + p1];

    uint32_t h, l;
    split2(v0, v1, h, l);
    ((uint32_t*)Wh)[idx] = h;
    ((uint32_t*)Wl)[idx] = l;
}

// ---------------- split fp32 activation into bf16 hi/lo --------------------
__global__ void split_kernel(const float* __restrict__ in,
                             __nv_bfloat16* __restrict__ hi,
                             __nv_bfloat16* __restrict__ lo) {
    int i = blockIdx.x * blockDim.x + threadIdx.x;     // float4 index
    float4 v = ((const float4*)in)[i];
    uint32_t h0, l0, h1, l1;
    split2(v.x, v.y, h0, l0);
    split2(v.z, v.w, h1, l1);
    ((uint2*)hi)[i] = make_uint2(h0, h1);
    ((uint2*)lo)[i] = make_uint2(l0, l1);
}

// ---------------- fused quaternion RoPE + bf16 split ------------------------
__global__ void rope_split_kernel(const float* __restrict__ q,
                                  __nv_bfloat16* __restrict__ hi,
                                  __nv_bfloat16* __restrict__ lo) {
    int idx = blockIdx.x * blockDim.x + threadIdx.x;   // group index
    int g = idx & 15;
    int s = (idx >> 8) & 2047;

    float4 v = ((const float4*)q)[idx];
    float ang = (float)s * powf(10000.0f, -(float)g / 16.0f);
    float cs = cosf(ang), sn = sinf(ang);
    int ax = g % 3;
    float ui = (ax == 0) ? sn : 0.f;
    float uj = (ax == 1) ? sn : 0.f;
    float uk = (ax == 2) ? sn : 0.f;
    float xr = v.x, xi = v.y, xj = v.z, xk = v.w;
    float4 o;
    o.x = cs * xr - ui * xi - uj * xj - uk * xk;
    o.y = cs * xi + ui * xr + uj * xk - uk * xj;
    o.z = cs * xj - ui * xk + uj * xr + uk * xi;
    o.w = cs * xk + ui * xj - uj * xi + uk * xr;

    uint32_t h0, l0, h1, l1;
    split2(o.x, o.y, h0, l0);
    split2(o.z, o.w, h1, l1);
    ((uint2*)hi)[idx] = make_uint2(h0, h1);
    ((uint2*)lo)[idx] = make_uint2(l0, l1);
}

// ================= mma.sync bf16-split GEMM (pre-split inputs) =============
#define SMS   20
#define BUFU  10240
#define GEMM_SMEM (2 * BUFU * 4)

__global__ __launch_bounds__(256) void qgemm_bf16(
    const __nv_bfloat16* __restrict__ Ah, const __nv_bfloat16* __restrict__ Al,
    const __nv_bfloat16* __restrict__ Bh, const __nv_bfloat16* __restrict__ Bl,
    const float* __restrict__ bias, float* __restrict__ C) {
    extern __shared__ uint32_t smu[];
    const uint32_t sbase = smem_to_u32(smu);
    const int tid  = threadIdx.x;
    const int lane = tid & 31, wid = tid >> 5;
    const int g = lane >> 2, t = lane & 3;
    const int wm = wid & 1, wn = wid >> 1;
    const int bm = blockIdx.y * 128, bn = blockIdx.x * 128;

    float acc[4][4][4];
    #pragma unroll
    for (int i = 0; i < 4; i++)
        #pragma unroll
        for (int j = 0; j < 4; j++)
            #pragma unroll
            for (int q = 0; q < 4; q++) acc[i][j][q] = 0.f;

    const int crow0 = tid >> 2;
    const int ccol  = tid & 3;
    const __nv_bfloat16* pAh = Ah + (size_t)(bm + crow0) * DIM + ccol * 8;
    const __nv_bfloat16* pAl = Al + (size_t)(bm + crow0) * DIM + ccol * 8;
    const __nv_bfloat16* pBh = Bh + (size_t)(bn + crow0) * DIM + ccol * 8;
    const __nv_bfloat16* pBl = Bl + (size_t)(bn + crow0) * DIM + ccol * 8;
    const uint32_t doff0 = (uint32_t)(crow0 * SMS + ccol * 4) * 4;
    const uint32_t rstep = (uint32_t)(64 * SMS) * 4;

    #define ISSUE_SLAB(s, b) do {                                              \
        int _k0 = (s) * 32;                                                    \
        uint32_t _d = sbase + (uint32_t)(b) * (BUFU * 4) + doff0;              \
        cp_async16(_d,                 pAh + _k0);                             \
        cp_async16(_d + rstep,         pAh + _k0 + (size_t)64 * DIM);          \
        cp_async16(_d + 2560*4,         pAl + _k0);                            \
        cp_async16(_d + 2560*4 + rstep, pAl + _k0 + (size_t)64 * DIM);         \
        cp_async16(_d + 5120*4,         pBh + _k0);                            \
        cp_async16(_d + 5120*4 + rstep, pBh + _k0 + (size_t)64 * DIM);         \
        cp_async16(_d + 7680*4,         pBl + _k0);                            \
        cp_async16(_d + 7680*4 + rstep, pBl + _k0 + (size_t)64 * DIM);         \
        CP_COMMIT();                                                           \
    } while (0)

    ISSUE_SLAB(0, 0);

    for (int s = 0; s < 32; s++) {
        const int cb = s & 1, nb = cb ^ 1;
        if (s + 1 < 32) {
            ISSUE_SLAB(s + 1, nb);
            CP_WAIT(1);
        } else {
            CP_WAIT(0);
        }
        __syncthreads();

        const uint32_t* base = smu + cb * BUFU;
        #pragma unroll
        for (int kk = 0; kk < 2; kk++) {
            uint32_t ah[4][4], al[4][4];
            #pragma unroll
            for (int mi = 0; mi < 4; mi++) {
                int r0 = (wm * 64 + mi * 16 + g) * SMS + kk * 8 + t;
                ah[mi][0] = base[r0];            ah[mi][1] = base[r0 + 8 * SMS];
                ah[mi][2] = base[r0 + 4];        ah[mi][3] = base[r0 + 8 * SMS + 4];
                al[mi][0] = base[2560 + r0];     al[mi][1] = base[2560 + r0 + 8 * SMS];
                al[mi][2] = base[2560 + r0 + 4]; al[mi][3] = base[2560 + r0 + 8 * SMS + 4];
            }
            uint32_t bh[4][2], bl[4][2];
            #pragma unroll
            for (int nj = 0; nj < 4; nj++) {
                int rn = (wn * 32 + nj * 8 + g) * SMS + kk * 8 + t;
                bh[nj][0] = base[5120 + rn]; bh[nj][1] = base[5120 + rn + 4];
                bl[nj][0] = base[7680 + rn]; bl[nj][1] = base[7680 + rn + 4];
            }
            #pragma unroll
            for (int mi = 0; mi < 4; mi++)
                #pragma unroll
                for (int nj = 0; nj < 4; nj++) {
                    mma16816(acc[mi][nj], ah[mi], bh[nj]);
                    mma16816(acc[mi][nj], ah[mi], bl[nj]);
                    mma16816(acc[mi][nj], al[mi], bh[nj]);
                }
        }
        __syncthreads();
    }

    #pragma unroll
    for (int mi = 0; mi < 4; mi++) {
        int row = bm + wm * 64 + mi * 16 + g;
        #pragma unroll
        for (int nj = 0; nj < 4; nj++) {
            int col = bn + wn * 32 + nj * 8 + 2 * t;
            float bx = bias[col], by = bias[col + 1];
            float2 v;
            v.x = acc[mi][nj][0] + bx; v.y = acc[mi][nj][1] + by;
            *(float2*)&C[(size_t)row * DIM + col] = v;
            v.x = acc[mi][nj][2] + bx; v.y = acc[mi][nj][3] + by;
            *(float2*)&C[(size_t)(row + 8) * DIM + col] = v;
        }
    }
}

// ================= tensor-core causal flash attention ======================
// 128 queries x 64 keys per iteration, 8 warps (16 rows each), DH=64.
// QK^T and PV both use 3-product bf16 split for fp32-grade accuracy.
// smem: Q stage (128 rows x 144B x hi/lo) unioned with K/V tiles
//   (Kh@0, Kl@9216, Vh@18432, Vl@27648; 64 rows x 144B each).
#define ATT_STRIDE 144
__global__ __launch_bounds__(256) void attn_tc(
    const __nv_bfloat16* __restrict__ Qh, const __nv_bfloat16* __restrict__ Ql,
    const __nv_bfloat16* __restrict__ Kh, const __nv_bfloat16* __restrict__ Kl,
    const __nv_bfloat16* __restrict__ Vh, const __nv_bfloat16* __restrict__ Vl,
    float* __restrict__ Out) {
    __shared__ __align__(16) char sm[36864];
    const uint32_t sb = smem_to_u32(sm);
    const int tid = threadIdx.x, lane = tid & 31, wid = tid >> 5;
    const int g = lane >> 2, t = lane & 3;
    const int qt = blockIdx.x, bh = blockIdx.y;
    const int b = bh >> 4, h = bh & 15;
    const int qb = qt * 128;
    const size_t rbase = (size_t)b * SQ;
    const int hoff = h * DH;

    // ---- stage Q tile hi/lo and extract fragments ----
    #pragma unroll
    for (int i = 0; i < 8; i++) {
        int half = i >> 2;
        int rem  = tid + 256 * (i & 3);       // 0..1023
        int r = rem >> 3, c = rem & 7;
        const __nv_bfloat16* src = (half ? Ql : Qh) + (rbase + qb + r) * DIM + hoff + c * 8;
        cp_async16(sb + half * 18432 + r * ATT_STRIDE + c * 16, src);
    }
    CP_COMMIT(); CP_WAIT(0);
    __syncthreads();

    uint32_t qfh[4][4], qfl[4][4];
    {
        uint32_t abase = sb + (wid * 16 + (lane & 15)) * ATT_STRIDE + (lane >> 4) * 16;
        #pragma unroll
        for (int kc = 0; kc < 4; kc++) {
            ldmatrix_x4(qfh[kc], abase + kc * 32);
            ldmatrix_x4(qfl[kc], abase + kc * 32 + 18432);
        }
    }
    __syncthreads();

    float Oa[8][4];
    #pragma unroll
    for (int j = 0; j < 8; j++)
        #pragma unroll
        for (int e = 0; e < 4; e++) Oa[j][e] = 0.f;
    float m0 = -1e30f, m1 = -1e30f, l0 = 0.f, l1 = 0.f;
    const int r0 = qb + wid * 16 + g;       // this thread's even row (local s index)
    const int ntiles = 2 * qt + 2;

    const __nv_bfloat16* kv0 = Kh + rbase * DIM + hoff;
    const __nv_bfloat16* kv1 = Kl + rbase * DIM + hoff;
    const __nv_bfloat16* kv2 = Vh + rbase * DIM + hoff;
    const __nv_bfloat16* kv3 = Vl + rbase * DIM + hoff;

    for (int jt = 0; jt < ntiles; jt++) {
        const int kb = jt * 64;
        // ---- load K/V tiles (hi/lo) ----
        #pragma unroll
        for (int i = 0; i < 8; i++) {
            int rem = (i & 1) ? tid + 256 : tid;   // 0..511
            int r = rem >> 3, c = rem & 7;
            const __nv_bfloat16* src =
                (i >> 1) == 0 ? kv0 : (i >> 1) == 1 ? kv1 : (i >> 1) == 2 ? kv2 : kv3;
            cp_async16(sb + (i >> 1) * 9216 + r * ATT_STRIDE + c * 16,
                       src + (size_t)(kb + r) * DIM + c * 8);
        }
        CP_COMMIT(); CP_WAIT(0);
        __syncthreads();

        // ---- S = Q K^T (3-product split) ----
        float S[8][4];
        #pragma unroll
        for (int j = 0; j < 8; j++)
            #pragma unroll
            for (int e = 0; e < 4; e++) S[j][e] = 0.f;

        #pragma unroll
        for (int kc = 0; kc < 4; kc++) {
            uint32_t bkh[8][2], bkl[8][2];
            uint32_t kaddr = sb + ((lane & 7)) * ATT_STRIDE + kc * 32 + ((lane >> 3) & 1) * 16;
            #pragma unroll
            for (int j = 0; j < 8; j++) {
                ldmatrix_x2(bkh[j], kaddr + j * 8 * ATT_STRIDE);
                ldmatrix_x2(bkl[j], kaddr + j * 8 * ATT_STRIDE + 9216);
            }
            #pragma unroll
            for (int j = 0; j < 8; j++) {
                mma16816(S[j], qfh[kc], bkh[j]);
                mma16816(S[j], qfh[kc], bkl[j]);
                mma16816(S[j], qfl[kc], bkh[j]);
            }
        }

        // ---- scale + causal mask ----
        const bool domask = (kb + 63 > qb);
        #pragma unroll
        for (int j = 0; j < 8; j++) {
            #pragma unroll
            for (int e = 0; e < 4; e++) S[j][e] *= 0.125f;
            if (domask) {
                int k0 = kb + 8 * j + 2 * t;
                if (k0     > r0    ) S[j][0] = -1e30f;
                if (k0 + 1 > r0    ) S[j][1] = -1e30f;
                if (k0     > r0 + 8) S[j][2] = -1e30f;
                if (k0 + 1 > r0 + 8) S[j][3] = -1e30f;
            }
        }

        // ---- online softmax ----
        float tm0 = -1e30f, tm1 = -1e30f;
        #pragma unroll
        for (int j = 0; j < 8; j++) {
            tm0 = fmaxf(tm0, fmaxf(S[j][0], S[j][1]));
            tm1 = fmaxf(tm1, fmaxf(S[j][2], S[j][3]));
        }
        tm0 = fmaxf(tm0, __shfl_xor_sync(0xFFFFFFFFu, tm0, 1));
        tm0 = fmaxf(tm0, __shfl_xor_sync(0xFFFFFFFFu, tm0, 2));
        tm1 = fmaxf(tm1, __shfl_xor_sync(0xFFFFFFFFu, tm1, 1));
        tm1 = fmaxf(tm1, __shfl_xor_sync(0xFFFFFFFFu, tm1, 2));
        float mn0 = fmaxf(m0, tm0), mn1 = fmaxf(m1, tm1);
        float sc0 = __expf(m0 - mn0), sc1 = __expf(m1 - mn1);
        m0 = mn0; m1 = mn1;
        l0 *= sc0; l1 *= sc1;
        #pragma unroll
        for (int j = 0; j < 8; j++) {
            Oa[j][0] *= sc0; Oa[j][1] *= sc0;
            Oa[j][2] *= sc1; Oa[j][3] *= sc1;
        }
        #pragma unroll
        for (int j = 0; j < 8; j++) {
            S[j][0] = __expf(S[j][0] - mn0); l0 += S[j][0];
            S[j][1] = __expf(S[j][1] - mn0); l0 += S[j][1];
            S[j][2] = __expf(S[j][2] - mn1); l1 += S[j][2];
            S[j][3] = __expf(S[j][3] - mn1); l1 += S[j][3];
        }

        // ---- O += P V (3-product split) ----
        #pragma unroll
        for (int c = 0; c < 4; c++) {
            uint32_t pah[4], pal[4];
            split2(S[2*c  ][0], S[2*c  ][1], pah[0], pal[0]);
            split2(S[2*c  ][2], S[2*c  ][3], pah[1], pal[1]);
            split2(S[2*c+1][0], S[2*c+1][1], pah[2], pal[2]);
            split2(S[2*c+1][2], S[2*c+1][3], pah[3], pal[3]);
            uint32_t vaddr = sb + 18432 + (16 * c + (lane & 15)) * ATT_STRIDE;
            #pragma unroll
            for (int j = 0; j < 8; j++) {
                uint32_t bvh[2], bvl[2];
                ldmatrix_x2_trans(bvh, vaddr + j * 16);
                ldmatrix_x2_trans(bvl, vaddr + j * 16 + 9216);
                mma16816(Oa[j], pah, bvh);
                mma16816(Oa[j], pah, bvl);
                mma16816(Oa[j], pal, bvh);
            }
        }
        __syncthreads();
    }

    // ---- finalize ----
    l0 += __shfl_xor_sync(0xFFFFFFFFu, l0, 1);
    l0 += __shfl_xor_sync(0xFFFFFFFFu, l0, 2);
    l1 += __shfl_xor_sync(0xFFFFFFFFu, l1, 1);
    l1 += __shfl_xor_sync(0xFFFFFFFFu, l1, 2);
    float inv0 = 1.f / l0, inv1 = 1.f / l1;
    float* o0 = Out + (rbase + r0) * DIM + hoff + 2 * t;
    float* o1 = Out + (rbase + r0 + 8) * DIM + hoff + 2 * t;
    #pragma unroll
    for (int j = 0; j < 8; j++) {
        float2 v;
        v.x = Oa[j][0] * inv0; v.y = Oa[j][1] * inv0;
        *(float2*)&o0[8 * j] = v;
        v.x = Oa[j][2] * inv1; v.y = Oa[j][3] * inv1;
        *(float2*)&o1[8 * j] = v;
    }
}

// ---------------- launch ---------------------------------------------------
extern "C" void kernel_launch(void* const* d_in, const int* in_sizes, int n_in,
                              void* d_out, int out_size) {
    const float* x = (const float*)d_in[0];
    // d_in[1] = mask (pure causal triu, ignored)
    const float* q_w[4] = {(const float*)d_in[2], (const float*)d_in[3],
                           (const float*)d_in[4], (const float*)d_in[5]};
    const float* q_b = (const float*)d_in[6];
    const float* k_w[4] = {(const float*)d_in[7], (const float*)d_in[8],
                           (const float*)d_in[9], (const float*)d_in[10]};
    const float* k_b = (const float*)d_in[11];
    const float* v_w[4] = {(const float*)d_in[12], (const float*)d_in[13],
                           (const float*)d_in[14], (const float*)d_in[15]};
    const float* v_b = (const float*)d_in[16];
    const float* o_w[4] = {(const float*)d_in[17], (const float*)d_in[18],
                           (const float*)d_in[19], (const float*)d_in[20]};
    const float* o_b = (const float*)d_in[21];

    __nv_bfloat16 *wh, *wl, *ah, *al, *qh, *ql, *kh, *kl, *vh, *vl;
    float *qb_, *kb_, *vb_, *ab;
    cudaGetSymbolAddress((void**)&wh, g_wh);
    cudaGetSymbolAddress((void**)&wl, g_wl);
    cudaGetSymbolAddress((void**)&ah, g_ah);
    cudaGetSymbolAddress((void**)&al, g_al);
    cudaGetSymbolAddress((void**)&qh, g_qh);
    cudaGetSymbolAddress((void**)&ql, g_ql);
    cudaGetSymbolAddress((void**)&kh, g_kh);
    cudaGetSymbolAddress((void**)&kl, g_kl);
    cudaGetSymbolAddress((void**)&vh, g_vh);
    cudaGetSymbolAddress((void**)&vl, g_vl);
    cudaGetSymbolAddress((void**)&qb_, g_q);
    cudaGetSymbolAddress((void**)&kb_, g_k);
    cudaGetSymbolAddress((void**)&vb_, g_v);
    cudaGetSymbolAddress((void**)&ab, g_attn);

    __nv_bfloat16* Wh[4];
    __nv_bfloat16* Wl[4];
    for (int i = 0; i < 4; i++) {
        Wh[i] = wh + (size_t)i * DIM * DIM;
        Wl[i] = wl + (size_t)i * DIM * DIM;
    }

    cudaFuncSetAttribute(qgemm_bf16, cudaFuncAttributeMaxDynamicSharedMemorySize,
                         GEMM_SMEM);

    const int wblocks = (DIM * DIM / 2) / 256;
    build_w_split_kernel<<<wblocks, 256>>>(q_w[0], q_w[1], q_w[2], q_w[3], Wh[0], Wl[0]);
    build_w_split_kernel<<<wblocks, 256>>>(k_w[0], k_w[1], k_w[2], k_w[3], Wh[1], Wl[1]);
    build_w_split_kernel<<<wblocks, 256>>>(v_w[0], v_w[1], v_w[2], v_w[3], Wh[2], Wl[2]);
    build_w_split_kernel<<<wblocks, 256>>>(o_w[0], o_w[1], o_w[2], o_w[3], Wh[3], Wl[3]);

    const int sblocks = (MROW * DIM / 4) / 256;
    split_kernel<<<sblocks, 256>>>(x, ah, al);

    dim3 ggrid(DIM / 128, MROW / 128);   // (8, 32)
    qgemm_bf16<<<ggrid, 256, GEMM_SMEM>>>(ah, al, Wh[0], Wl[0], q_b, qb_);
    qgemm_bf16<<<ggrid, 256, GEMM_SMEM>>>(ah, al, Wh[1], Wl[1], k_b, kb_);
    qgemm_bf16<<<ggrid, 256, GEMM_SMEM>>>(ah, al, Wh[2], Wl[2], v_b, vb_);

    const int ngroups = BQ * SQ * HQ * GQ;     // 1M
    rope_split_kernel<<<ngroups / 256, 256>>>(qb_, qh, ql);
    rope_split_kernel<<<ngroups / 256, 256>>>(kb_, kh, kl);
    split_kernel<<<sblocks, 256>>>(vb_, vh, vl);

    dim3 agrid(SQ / 128, BQ * HQ);             // (16, 32)
    attn_tc<<<agrid, 256>>>(qh, ql, kh, kl, vh, vl, ab);

    split_kernel<<<sblocks, 256>>>(ab, ah, al);
    qgemm_bf16<<<ggrid, 256, GEMM_SMEM>>>(ah, al, Wh[3], Wl[3], o_b, (float*)d_out);
}

// round 7
// speedup vs baseline: 3.0842x; 1.1427x over previous
#include <cuda_runtime.h>
#include <cuda_bf16.h>
#include <math.h>
#include <cstdint>

#define BQ   2
#define SQ   2048
#define DIM  1024
#define HQ   16
#define DH   64
#define GQ   16
#define IQ   256
#define MROW (BQ*SQ)   /* 4096 */

// ---------------- device scratch (no allocations allowed) ----------------
__device__ __nv_bfloat16 g_wh[4][DIM*DIM];   // W_eff hi, [n][k]
__device__ __nv_bfloat16 g_wl[4][DIM*DIM];   // W_eff lo
__device__ __nv_bfloat16 g_ah[MROW*DIM];     // activation hi (x, later attn out)
__device__ __nv_bfloat16 g_al[MROW*DIM];     // activation lo
__device__ __nv_bfloat16 g_qh[MROW*DIM];
__device__ __nv_bfloat16 g_ql[MROW*DIM];
__device__ __nv_bfloat16 g_kh[MROW*DIM];
__device__ __nv_bfloat16 g_kl[MROW*DIM];
__device__ __nv_bfloat16 g_vh[MROW*DIM];
__device__ __nv_bfloat16 g_vl[MROW*DIM];
__device__ float g_q[MROW*DIM];
__device__ float g_k[MROW*DIM];

// ---------------- helpers --------------------------------------------------
__device__ __forceinline__ uint32_t smem_to_u32(const void* p) {
    uint32_t a;
    asm("{ .reg .u64 t; cvta.to.shared.u64 t, %1; cvt.u32.u64 %0, t; }"
        : "=r"(a) : "l"(p));
    return a;
}
__device__ __forceinline__ void cp_async16(uint32_t dst, const void* src) {
    asm volatile("cp.async.ca.shared.global [%0], [%1], 16;"
                 :: "r"(dst), "l"(src));
}
#define CP_COMMIT() asm volatile("cp.async.commit_group;" ::: "memory")
#define CP_WAIT(n)  asm volatile("cp.async.wait_group %0;" :: "n"(n) : "memory")

// split fp32 pair into bf16x2 hi (x low half, y high half) and lo
__device__ __forceinline__ void split2(float x, float y, uint32_t& hi, uint32_t& lo) {
    uint32_t h;
    asm("cvt.rn.bf16x2.f32 %0, %1, %2;" : "=r"(h) : "f"(y), "f"(x));
    float xh = __uint_as_float(h << 16);
    float yh = __uint_as_float(h & 0xFFFF0000u);
    float xl = x - xh, yl = y - yh;
    uint32_t l;
    asm("cvt.rn.bf16x2.f32 %0, %1, %2;" : "=r"(l) : "f"(yl), "f"(xl));
    hi = h; lo = l;
}

__device__ __forceinline__ void mma16816(float* c, const uint32_t* a, const uint32_t* b) {
    asm volatile(
        "mma.sync.aligned.m16n8k16.row.col.f32.bf16.bf16.f32 "
        "{%0,%1,%2,%3}, {%4,%5,%6,%7}, {%8,%9}, {%0,%1,%2,%3};"
        : "+f"(c[0]), "+f"(c[1]), "+f"(c[2]), "+f"(c[3])
        : "r"(a[0]), "r"(a[1]), "r"(a[2]), "r"(a[3]), "r"(b[0]), "r"(b[1]));
}
__device__ __forceinline__ void ldmatrix_x4(uint32_t* r, uint32_t addr) {
    asm volatile("ldmatrix.sync.aligned.m8n8.x4.shared.b16 {%0,%1,%2,%3}, [%4];"
                 : "=r"(r[0]), "=r"(r[1]), "=r"(r[2]), "=r"(r[3]) : "r"(addr));
}
__device__ __forceinline__ void ldmatrix_x2(uint32_t* r, uint32_t addr) {
    asm volatile("ldmatrix.sync.aligned.m8n8.x2.shared.b16 {%0,%1}, [%2];"
                 : "=r"(r[0]), "=r"(r[1]) : "r"(addr));
}
__device__ __forceinline__ void ldmatrix_x2_trans(uint32_t* r, uint32_t addr) {
    asm volatile("ldmatrix.sync.aligned.m8n8.x2.trans.shared.b16 {%0,%1}, [%2];"
                 : "=r"(r[0]), "=r"(r[1]) : "r"(addr));
}

// ---------------- build effective quaternion weight, split to bf16 --------
// thread = (n, p): 4 coalesced loads (same offset in wr/wi/wj/wk),
// emits k = 4p..4p+3 of row n as hi/lo uint2. Fully coalesced.
__global__ void build_w_split_kernel(const float* __restrict__ wr,
                                     const float* __restrict__ wi,
                                     const float* __restrict__ wj,
                                     const float* __restrict__ wk,
                                     __nv_bfloat16* __restrict__ Wh,
                                     __nv_bfloat16* __restrict__ Wl) {
    int idx = blockIdx.x * blockDim.x + threadIdx.x;   // 0 .. DIM*IQ-1
    int n = idx >> 8;          // 0..1023
    int p = idx & 255;         // 0..255
    int m = n >> 2, c = n & 3;

    int off = m * IQ + p;
    float r = wr[off], i = wi[off], j = wj[off], k = wk[off];

    // Hamilton rows: value for (c, d)
    float v0, v1, v2, v3;
    switch (c) {
        case 0: v0 =  r; v1 = -i; v2 = -j; v3 = -k; break;
        case 1: v0 =  i; v1 =  r; v2 = -j; v3 =  k; break;
        case 2: v0 =  j; v1 =  i; v2 =  r; v3 = -k; break;
        default: v0 = k; v1 = -i; v2 =  j; v3 =  r; break;
    }

    uint32_t h0, l0, h1, l1;
    split2(v0, v1, h0, l0);
    split2(v2, v3, h1, l1);
    size_t o = ((size_t)n * DIM + 4 * p) >> 1;   // uint32 index
    ((uint2*)Wh)[o >> 1] = make_uint2(h0, h1);
    ((uint2*)Wl)[o >> 1] = make_uint2(l0, l1);
}

// ---------------- split fp32 activation into bf16 hi/lo --------------------
__global__ void split_kernel(const float* __restrict__ in,
                             __nv_bfloat16* __restrict__ hi,
                             __nv_bfloat16* __restrict__ lo) {
    int i = blockIdx.x * blockDim.x + threadIdx.x;     // float4 index
    float4 v = ((const float4*)in)[i];
    uint32_t h0, l0, h1, l1;
    split2(v.x, v.y, h0, l0);
    split2(v.z, v.w, h1, l1);
    ((uint2*)hi)[i] = make_uint2(h0, h1);
    ((uint2*)lo)[i] = make_uint2(l0, l1);
}

// ---------------- fused quaternion RoPE + bf16 split ------------------------
__global__ void rope_split_kernel(const float* __restrict__ q,
                                  __nv_bfloat16* __restrict__ hi,
                                  __nv_bfloat16* __restrict__ lo) {
    int idx = blockIdx.x * blockDim.x + threadIdx.x;   // group index
    int g = idx & 15;
    int s = (idx >> 8) & 2047;

    float4 v = ((const float4*)q)[idx];
    float ang = (float)s * powf(10000.0f, -(float)g / 16.0f);
    float cs = cosf(ang), sn = sinf(ang);
    int ax = g % 3;
    float ui = (ax == 0) ? sn : 0.f;
    float uj = (ax == 1) ? sn : 0.f;
    float uk = (ax == 2) ? sn : 0.f;
    float xr = v.x, xi = v.y, xj = v.z, xk = v.w;
    float4 o;
    o.x = cs * xr - ui * xi - uj * xj - uk * xk;
    o.y = cs * xi + ui * xr + uj * xk - uk * xj;
    o.z = cs * xj - ui * xk + uj * xr + uk * xi;
    o.w = cs * xk + ui * xj - uj * xi + uk * xr;

    uint32_t h0, l0, h1, l1;
    split2(o.x, o.y, h0, l0);
    split2(o.z, o.w, h1, l1);
    ((uint2*)hi)[idx] = make_uint2(h0, h1);
    ((uint2*)lo)[idx] = make_uint2(l0, l1);
}

// ================= mma.sync bf16-split GEMM (pre-split inputs) =============
// OUTMODE 0: fp32 C.  OUTMODE 1: bf16 hi/lo (Ch/Cl) split in epilogue.
#define SMS   20
#define BUFU  10240
#define GEMM_SMEM (2 * BUFU * 4)

template <int OUTMODE>
__global__ __launch_bounds__(256) void qgemm_bf16(
    const __nv_bfloat16* __restrict__ Ah, const __nv_bfloat16* __restrict__ Al,
    const __nv_bfloat16* __restrict__ Bh, const __nv_bfloat16* __restrict__ Bl,
    const float* __restrict__ bias, float* __restrict__ C,
    __nv_bfloat16* __restrict__ Ch, __nv_bfloat16* __restrict__ Cl) {
    extern __shared__ uint32_t smu[];
    const uint32_t sbase = smem_to_u32(smu);
    const int tid  = threadIdx.x;
    const int lane = tid & 31, wid = tid >> 5;
    const int g = lane >> 2, t = lane & 3;
    const int wm = wid & 1, wn = wid >> 1;
    const int bm = blockIdx.y * 128, bn = blockIdx.x * 128;

    float acc[4][4][4];
    #pragma unroll
    for (int i = 0; i < 4; i++)
        #pragma unroll
        for (int j = 0; j < 4; j++)
            #pragma unroll
            for (int q = 0; q < 4; q++) acc[i][j][q] = 0.f;

    const int crow0 = tid >> 2;
    const int ccol  = tid & 3;
    const __nv_bfloat16* pAh = Ah + (size_t)(bm + crow0) * DIM + ccol * 8;
    const __nv_bfloat16* pAl = Al + (size_t)(bm + crow0) * DIM + ccol * 8;
    const __nv_bfloat16* pBh = Bh + (size_t)(bn + crow0) * DIM + ccol * 8;
    const __nv_bfloat16* pBl = Bl + (size_t)(bn + crow0) * DIM + ccol * 8;
    const uint32_t doff0 = (uint32_t)(crow0 * SMS + ccol * 4) * 4;
    const uint32_t rstep = (uint32_t)(64 * SMS) * 4;

    #define ISSUE_SLAB(s, b) do {                                              \
        int _k0 = (s) * 32;                                                    \
        uint32_t _d = sbase + (uint32_t)(b) * (BUFU * 4) + doff0;              \
        cp_async16(_d,                 pAh + _k0);                             \
        cp_async16(_d + rstep,         pAh + _k0 + (size_t)64 * DIM);          \
        cp_async16(_d + 2560*4,         pAl + _k0);                            \
        cp_async16(_d + 2560*4 + rstep, pAl + _k0 + (size_t)64 * DIM);         \
        cp_async16(_d + 5120*4,         pBh + _k0);                            \
        cp_async16(_d + 5120*4 + rstep, pBh + _k0 + (size_t)64 * DIM);         \
        cp_async16(_d + 7680*4,         pBl + _k0);                            \
        cp_async16(_d + 7680*4 + rstep, pBl + _k0 + (size_t)64 * DIM);         \
        CP_COMMIT();                                                           \
    } while (0)

    ISSUE_SLAB(0, 0);

    for (int s = 0; s < 32; s++) {
        const int cb = s & 1, nb = cb ^ 1;
        if (s + 1 < 32) {
            ISSUE_SLAB(s + 1, nb);
            CP_WAIT(1);
        } else {
            CP_WAIT(0);
        }
        __syncthreads();

        const uint32_t* base = smu + cb * BUFU;
        #pragma unroll
        for (int kk = 0; kk < 2; kk++) {
            uint32_t ah[4][4], al[4][4];
            #pragma unroll
            for (int mi = 0; mi < 4; mi++) {
                int r0 = (wm * 64 + mi * 16 + g) * SMS + kk * 8 + t;
                ah[mi][0] = base[r0];            ah[mi][1] = base[r0 + 8 * SMS];
                ah[mi][2] = base[r0 + 4];        ah[mi][3] = base[r0 + 8 * SMS + 4];
                al[mi][0] = base[2560 + r0];     al[mi][1] = base[2560 + r0 + 8 * SMS];
                al[mi][2] = base[2560 + r0 + 4]; al[mi][3] = base[2560 + r0 + 8 * SMS + 4];
            }
            uint32_t bh[4][2], bl[4][2];
            #pragma unroll
            for (int nj = 0; nj < 4; nj++) {
                int rn = (wn * 32 + nj * 8 + g) * SMS + kk * 8 + t;
                bh[nj][0] = base[5120 + rn]; bh[nj][1] = base[5120 + rn + 4];
                bl[nj][0] = base[7680 + rn]; bl[nj][1] = base[7680 + rn + 4];
            }
            #pragma unroll
            for (int mi = 0; mi < 4; mi++)
                #pragma unroll
                for (int nj = 0; nj < 4; nj++) {
                    mma16816(acc[mi][nj], ah[mi], bh[nj]);
                    mma16816(acc[mi][nj], ah[mi], bl[nj]);
                    mma16816(acc[mi][nj], al[mi], bh[nj]);
                }
        }
        __syncthreads();
    }

    #pragma unroll
    for (int mi = 0; mi < 4; mi++) {
        int row = bm + wm * 64 + mi * 16 + g;
        #pragma unroll
        for (int nj = 0; nj < 4; nj++) {
            int col = bn + wn * 32 + nj * 8 + 2 * t;
            float bx = bias[col], by = bias[col + 1];
            if (OUTMODE == 0) {
                float2 v;
                v.x = acc[mi][nj][0] + bx; v.y = acc[mi][nj][1] + by;
                *(float2*)&C[(size_t)row * DIM + col] = v;
                v.x = acc[mi][nj][2] + bx; v.y = acc[mi][nj][3] + by;
                *(float2*)&C[(size_t)(row + 8) * DIM + col] = v;
            } else {
                uint32_t h, l;
                split2(acc[mi][nj][0] + bx, acc[mi][nj][1] + by, h, l);
                *(uint32_t*)&Ch[(size_t)row * DIM + col] = h;
                *(uint32_t*)&Cl[(size_t)row * DIM + col] = l;
                split2(acc[mi][nj][2] + bx, acc[mi][nj][3] + by, h, l);
                *(uint32_t*)&Ch[(size_t)(row + 8) * DIM + col] = h;
                *(uint32_t*)&Cl[(size_t)(row + 8) * DIM + col] = l;
            }
        }
    }
}

// ================= tensor-core causal flash attention ======================
// 128 queries x 64 keys per iter, 8 warps, DH=64, double-buffered K/V tiles.
// Per stage (36864B): Kh@0, Kl@9216, Vh@18432, Vl@27648; 144B rows.
// Output written directly as bf16 hi/lo (split fused into epilogue).
#define ATT_STRIDE 144
#define ATT_STAGE  36864
#define ATT_SMEM   (2 * ATT_STAGE)
__global__ __launch_bounds__(256) void attn_tc(
    const __nv_bfloat16* __restrict__ Qh, const __nv_bfloat16* __restrict__ Ql,
    const __nv_bfloat16* __restrict__ Kh, const __nv_bfloat16* __restrict__ Kl,
    const __nv_bfloat16* __restrict__ Vh, const __nv_bfloat16* __restrict__ Vl,
    __nv_bfloat16* __restrict__ Oh, __nv_bfloat16* __restrict__ Ol) {
    extern __shared__ __align__(16) char sm[];
    const uint32_t sb = smem_to_u32(sm);
    const int tid = threadIdx.x, lane = tid & 31, wid = tid >> 5;
    const int g = lane >> 2, t = lane & 3;
    const int qt = blockIdx.x, bh = blockIdx.y;
    const int b = bh >> 4, h = bh & 15;
    const int qb = qt * 128;
    const size_t rbase = (size_t)b * SQ;
    const int hoff = h * DH;

    // ---- stage Q tile hi/lo and extract fragments ----
    #pragma unroll
    for (int i = 0; i < 8; i++) {
        int half = i >> 2;
        int rem  = tid + 256 * (i & 3);       // 0..1023
        int r = rem >> 3, c = rem & 7;
        const __nv_bfloat16* src = (half ? Ql : Qh) + (rbase + qb + r) * DIM + hoff + c * 8;
        cp_async16(sb + half * 18432 + r * ATT_STRIDE + c * 16, src);
    }
    CP_COMMIT(); CP_WAIT(0);
    __syncthreads();

    uint32_t qfh[4][4], qfl[4][4];
    {
        uint32_t abase = sb + (wid * 16 + (lane & 15)) * ATT_STRIDE + (lane >> 4) * 16;
        #pragma unroll
        for (int kc = 0; kc < 4; kc++) {
            ldmatrix_x4(qfh[kc], abase + kc * 32);
            ldmatrix_x4(qfl[kc], abase + kc * 32 + 18432);
        }
    }
    __syncthreads();

    float Oa[8][4];
    #pragma unroll
    for (int j = 0; j < 8; j++)
        #pragma unroll
        for (int e = 0; e < 4; e++) Oa[j][e] = 0.f;
    float m0 = -1e30f, m1 = -1e30f, l0 = 0.f, l1 = 0.f;
    const int r0 = qb + wid * 16 + g;
    const int ntiles = 2 * qt + 2;

    const __nv_bfloat16* kv0 = Kh + rbase * DIM + hoff;
    const __nv_bfloat16* kv1 = Kl + rbase * DIM + hoff;
    const __nv_bfloat16* kv2 = Vh + rbase * DIM + hoff;
    const __nv_bfloat16* kv3 = Vl + rbase * DIM + hoff;

    #define ISSUE_KV(jt_, st_) do {                                             \
        int _kb = (jt_) * 64;                                                   \
        uint32_t _s = sb + (uint32_t)(st_) * ATT_STAGE;                         \
        _Pragma("unroll")                                                       \
        for (int i = 0; i < 8; i++) {                                           \
            int rem = (i & 1) ? tid + 256 : tid;                                \
            int r = rem >> 3, c = rem & 7;                                      \
            const __nv_bfloat16* src =                                          \
                (i >> 1) == 0 ? kv0 : (i >> 1) == 1 ? kv1 :                     \
                (i >> 1) == 2 ? kv2 : kv3;                                      \
            cp_async16(_s + (i >> 1) * 9216 + r * ATT_STRIDE + c * 16,          \
                       src + (size_t)(_kb + r) * DIM + c * 8);                  \
        }                                                                       \
        CP_COMMIT();                                                            \
    } while (0)

    ISSUE_KV(0, 0);

    for (int jt = 0; jt < ntiles; jt++) {
        const int kb = jt * 64;
        const int cb = jt & 1, nb = cb ^ 1;
        if (jt + 1 < ntiles) {
            ISSUE_KV(jt + 1, nb);
            CP_WAIT(1);
        } else {
            CP_WAIT(0);
        }
        __syncthreads();
        const uint32_t stg = sb + (uint32_t)cb * ATT_STAGE;

        // ---- S = Q K^T (3-product split) ----
        float S[8][4];
        #pragma unroll
        for (int j = 0; j < 8; j++)
            #pragma unroll
            for (int e = 0; e < 4; e++) S[j][e] = 0.f;

        #pragma unroll
        for (int kc = 0; kc < 4; kc++) {
            uint32_t bkh[8][2], bkl[8][2];
            uint32_t kaddr = stg + (lane & 7) * ATT_STRIDE + kc * 32 + ((lane >> 3) & 1) * 16;
            #pragma unroll
            for (int j = 0; j < 8; j++) {
                ldmatrix_x2(bkh[j], kaddr + j * 8 * ATT_STRIDE);
                ldmatrix_x2(bkl[j], kaddr + j * 8 * ATT_STRIDE + 9216);
            }
            #pragma unroll
            for (int j = 0; j < 8; j++) {
                mma16816(S[j], qfh[kc], bkh[j]);
                mma16816(S[j], qfh[kc], bkl[j]);
                mma16816(S[j], qfl[kc], bkh[j]);
            }
        }

        // ---- scale + causal mask ----
        const bool domask = (kb + 63 > qb);
        #pragma unroll
        for (int j = 0; j < 8; j++) {
            #pragma unroll
            for (int e = 0; e < 4; e++) S[j][e] *= 0.125f;
            if (domask) {
                int k0 = kb + 8 * j + 2 * t;
                if (k0     > r0    ) S[j][0] = -1e30f;
                if (k0 + 1 > r0    ) S[j][1] = -1e30f;
                if (k0     > r0 + 8) S[j][2] = -1e30f;
                if (k0 + 1 > r0 + 8) S[j][3] = -1e30f;
            }
        }

        // ---- online softmax ----
        float tm0 = -1e30f, tm1 = -1e30f;
        #pragma unroll
        for (int j = 0; j < 8; j++) {
            tm0 = fmaxf(tm0, fmaxf(S[j][0], S[j][1]));
            tm1 = fmaxf(tm1, fmaxf(S[j][2], S[j][3]));
        }
        tm0 = fmaxf(tm0, __shfl_xor_sync(0xFFFFFFFFu, tm0, 1));
        tm0 = fmaxf(tm0, __shfl_xor_sync(0xFFFFFFFFu, tm0, 2));
        tm1 = fmaxf(tm1, __shfl_xor_sync(0xFFFFFFFFu, tm1, 1));
        tm1 = fmaxf(tm1, __shfl_xor_sync(0xFFFFFFFFu, tm1, 2));
        float mn0 = fmaxf(m0, tm0), mn1 = fmaxf(m1, tm1);
        float sc0 = __expf(m0 - mn0), sc1 = __expf(m1 - mn1);
        m0 = mn0; m1 = mn1;
        l0 *= sc0; l1 *= sc1;
        #pragma unroll
        for (int j = 0; j < 8; j++) {
            Oa[j][0] *= sc0; Oa[j][1] *= sc0;
            Oa[j][2] *= sc1; Oa[j][3] *= sc1;
        }
        #pragma unroll
        for (int j = 0; j < 8; j++) {
            S[j][0] = __expf(S[j][0] - mn0); l0 += S[j][0];
            S[j][1] = __expf(S[j][1] - mn0); l0 += S[j][1];
            S[j][2] = __expf(S[j][2] - mn1); l1 += S[j][2];
            S[j][3] = __expf(S[j][3] - mn1); l1 += S[j][3];
        }

        // ---- O += P V (3-product split) ----
        #pragma unroll
        for (int c = 0; c < 4; c++) {
            uint32_t pah[4], pal[4];
            split2(S[2*c  ][0], S[2*c  ][1], pah[0], pal[0]);
            split2(S[2*c  ][2], S[2*c  ][3], pah[1], pal[1]);
            split2(S[2*c+1][0], S[2*c+1][1], pah[2], pal[2]);
            split2(S[2*c+1][2], S[2*c+1][3], pah[3], pal[3]);
            uint32_t vaddr = stg + 18432 + (16 * c + (lane & 15)) * ATT_STRIDE;
            #pragma unroll
            for (int j = 0; j < 8; j++) {
                uint32_t bvh[2], bvl[2];
                ldmatrix_x2_trans(bvh, vaddr + j * 16);
                ldmatrix_x2_trans(bvl, vaddr + j * 16 + 9216);
                mma16816(Oa[j], pah, bvh);
                mma16816(Oa[j], pah, bvl);
                mma16816(Oa[j], pal, bvh);
            }
        }
        __syncthreads();
    }

    // ---- finalize: write bf16 hi/lo directly ----
    l0 += __shfl_xor_sync(0xFFFFFFFFu, l0, 1);
    l0 += __shfl_xor_sync(0xFFFFFFFFu, l0, 2);
    l1 += __shfl_xor_sync(0xFFFFFFFFu, l1, 1);
    l1 += __shfl_xor_sync(0xFFFFFFFFu, l1, 2);
    float inv0 = 1.f / l0, inv1 = 1.f / l1;
    size_t off0 = (rbase + r0) * DIM + hoff + 2 * t;
    size_t off1 = (rbase + r0 + 8) * DIM + hoff + 2 * t;
    #pragma unroll
    for (int j = 0; j < 8; j++) {
        uint32_t h, l;
        split2(Oa[j][0] * inv0, Oa[j][1] * inv0, h, l);
        *(uint32_t*)&Oh[off0 + 8 * j] = h;
        *(uint32_t*)&Ol[off0 + 8 * j] = l;
        split2(Oa[j][2] * inv1, Oa[j][3] * inv1, h, l);
        *(uint32_t*)&Oh[off1 + 8 * j] = h;
        *(uint32_t*)&Ol[off1 + 8 * j] = l;
    }
}

// ---------------- launch ---------------------------------------------------
extern "C" void kernel_launch(void* const* d_in, const int* in_sizes, int n_in,
                              void* d_out, int out_size) {
    const float* x = (const float*)d_in[0];
    // d_in[1] = mask (pure causal triu, ignored)
    const float* q_w[4] = {(const float*)d_in[2], (const float*)d_in[3],
                           (const float*)d_in[4], (const float*)d_in[5]};
    const float* q_b = (const float*)d_in[6];
    const float* k_w[4] = {(const float*)d_in[7], (const float*)d_in[8],
                           (const float*)d_in[9], (const float*)d_in[10]};
    const float* k_b = (const float*)d_in[11];
    const float* v_w[4] = {(const float*)d_in[12], (const float*)d_in[13],
                           (const float*)d_in[14], (const float*)d_in[15]};
    const float* v_b = (const float*)d_in[16];
    const float* o_w[4] = {(const float*)d_in[17], (const float*)d_in[18],
                           (const float*)d_in[19], (const float*)d_in[20]};
    const float* o_b = (const float*)d_in[21];

    __nv_bfloat16 *wh, *wl, *ah, *al, *qh, *ql, *kh, *kl, *vh, *vl;
    float *qb_, *kb_;
    cudaGetSymbolAddress((void**)&wh, g_wh);
    cudaGetSymbolAddress((void**)&wl, g_wl);
    cudaGetSymbolAddress((void**)&ah, g_ah);
    cudaGetSymbolAddress((void**)&al, g_al);
    cudaGetSymbolAddress((void**)&qh, g_qh);
    cudaGetSymbolAddress((void**)&ql, g_ql);
    cudaGetSymbolAddress((void**)&kh, g_kh);
    cudaGetSymbolAddress((void**)&kl, g_kl);
    cudaGetSymbolAddress((void**)&vh, g_vh);
    cudaGetSymbolAddress((void**)&vl, g_vl);
    cudaGetSymbolAddress((void**)&qb_, g_q);
    cudaGetSymbolAddress((void**)&kb_, g_k);

    __nv_bfloat16* Wh[4];
    __nv_bfloat16* Wl[4];
    for (int i = 0; i < 4; i++) {
        Wh[i] = wh + (size_t)i * DIM * DIM;
        Wl[i] = wl + (size_t)i * DIM * DIM;
    }

    cudaFuncSetAttribute(qgemm_bf16<0>, cudaFuncAttributeMaxDynamicSharedMemorySize,
                         GEMM_SMEM);
    cudaFuncSetAttribute(qgemm_bf16<1>, cudaFuncAttributeMaxDynamicSharedMemorySize,
                         GEMM_SMEM);
    cudaFuncSetAttribute(attn_tc, cudaFuncAttributeMaxDynamicSharedMemorySize,
                         ATT_SMEM);

    const int wblocks = (DIM * IQ) / 256;      // 1024 blocks
    build_w_split_kernel<<<wblocks, 256>>>(q_w[0], q_w[1], q_w[2], q_w[3], Wh[0], Wl[0]);
    build_w_split_kernel<<<wblocks, 256>>>(k_w[0], k_w[1], k_w[2], k_w[3], Wh[1], Wl[1]);
    build_w_split_kernel<<<wblocks, 256>>>(v_w[0], v_w[1], v_w[2], v_w[3], Wh[2], Wl[2]);
    build_w_split_kernel<<<wblocks, 256>>>(o_w[0], o_w[1], o_w[2], o_w[3], Wh[3], Wl[3]);

    const int sblocks = (MROW * DIM / 4) / 256;
    split_kernel<<<sblocks, 256>>>(x, ah, al);

    dim3 ggrid(DIM / 128, MROW / 128);   // (8, 32)
    qgemm_bf16<0><<<ggrid, 256, GEMM_SMEM>>>(ah, al, Wh[0], Wl[0], q_b, qb_, nullptr, nullptr);
    qgemm_bf16<0><<<ggrid, 256, GEMM_SMEM>>>(ah, al, Wh[1], Wl[1], k_b, kb_, nullptr, nullptr);
    qgemm_bf16<1><<<ggrid, 256, GEMM_SMEM>>>(ah, al, Wh[2], Wl[2], v_b, nullptr, vh, vl);

    const int ngroups = BQ * SQ * HQ * GQ;     // 1M
    rope_split_kernel<<<ngroups / 256, 256>>>(qb_, qh, ql);
    rope_split_kernel<<<ngroups / 256, 256>>>(kb_, kh, kl);

    dim3 agrid(SQ / 128, BQ * HQ);             // (16, 32)
    attn_tc<<<agrid, 256, ATT_SMEM>>>(qh, ql, kh, kl, vh, vl, ah, al);

    qgemm_bf16<0><<<ggrid, 256, GEMM_SMEM>>>(ah, al, Wh[3], Wl[3], o_b, (float*)d_out, nullptr, nullptr);
}